// round 5
// baseline (speedup 1.0000x reference)
#include <cuda_runtime.h>
#include <cuda_bf16.h>
#include <math.h>

// Shapes
#define BB 32
#define FF 4096
#define SS 8
#define DD 512
#define HH 2048
#define NCHUNK 32              // feature chunks per batch in streaming pass
#define ROWS_PER_CHUNK (FF / NCHUNK)   // 128
#define SCALE_QK 0.044194173824159216f // 512^-0.5
#define LN_EPS 1e-5f
#define ATTN_EPS 1e-8f

// ---------------- scratch (static device globals; no allocation) ----------------
__device__ float g_wqk [DD * DD];
__device__ float g_cur [BB * SS * DD];
__device__ float g_sn  [BB * SS * DD];
__device__ float g_qt  [BB * SS * DD];
__device__ float g_Up  [BB * NCHUNK * SS * DD];   // 16.8 MB
__device__ float g_Zp  [BB * NCHUNK * SS];
__device__ float g_un  [BB * SS * DD];
__device__ float g_upd [BB * SS * DD];
__device__ float g_gi  [BB * SS * 3 * DD];
__device__ float g_gh  [BB * SS * 3 * DD];
__device__ float g_h   [BB * SS * DD];
__device__ float g_a1  [BB * SS * HH];

// ---------------- helpers ----------------
__device__ __forceinline__ float wred(float v) {
    v += __shfl_xor_sync(0xffffffffu, v, 16);
    v += __shfl_xor_sync(0xffffffffu, v, 8);
    v += __shfl_xor_sync(0xffffffffu, v, 4);
    v += __shfl_xor_sync(0xffffffffu, v, 2);
    v += __shfl_xor_sync(0xffffffffu, v, 1);
    return v;
}

// ---------------- LayerNorm over rows of width 512 ----------------
// grid = nrows, block = 128 (4 elems/thread)
__global__ void ln_rows(const float* __restrict__ X, const float* __restrict__ w,
                        const float* __restrict__ b, float* __restrict__ Y) {
    int row = blockIdx.x;
    int tid = threadIdx.x;
    const float* x = X + (size_t)row * DD;
    float4 v = *(const float4*)&x[tid * 4];
    float s1 = v.x + v.y + v.z + v.w;
    float s2 = v.x * v.x + v.y * v.y + v.z * v.z + v.w * v.w;
    s1 = wred(s1); s2 = wred(s2);
    __shared__ float sm[8];
    int lane = tid & 31, wp = tid >> 5;
    if (lane == 0) { sm[wp] = s1; sm[4 + wp] = s2; }
    __syncthreads();
    float st  = sm[0] + sm[1] + sm[2] + sm[3];
    float s2t = sm[4] + sm[5] + sm[6] + sm[7];
    float m = st * (1.0f / DD);
    float var = s2t * (1.0f / DD) - m * m;
    float rstd = rsqrtf(var + LN_EPS);
    float4 wv = *(const float4*)&w[tid * 4];
    float4 bv = *(const float4*)&b[tid * 4];
    float4 o;
    o.x = (v.x - m) * rstd * wv.x + bv.x;
    o.y = (v.y - m) * rstd * wv.y + bv.y;
    o.z = (v.z - m) * rstd * wv.z + bv.z;
    o.w = (v.w - m) * rstd * wv.w + bv.w;
    *(float4*)&Y[(size_t)row * DD + tid * 4] = o;
}

// ---------------- generic 32x32 tiled GEMM ----------------
// C[M,N] = alpha * A[M,K] @ B (+bias +relu +res)
// TRANSB: B_logical[k][n] = W[n][k], W row-major [N,K]
template<bool TRANSB, bool BIAS, bool RELU, bool RES>
__global__ void __launch_bounds__(256) gemm32(
    const float* __restrict__ A, const float* __restrict__ B,
    const float* __restrict__ bias, const float* __restrict__ res,
    float* __restrict__ C, int M, int N, int K, float alpha) {
    __shared__ float As[32][36];
    __shared__ float Bs[32][36];
    int tid = threadIdx.x;
    int r  = tid >> 3;      // 0..31
    int cq = tid & 7;       // 0..7
    int tileM = blockIdx.y * 32;
    int tileN = blockIdx.x * 32;
    float acc0 = 0.f, acc1 = 0.f, acc2 = 0.f, acc3 = 0.f;
    for (int kc = 0; kc < K; kc += 32) {
        // stage A: thread (m=r, kq=cq)
        float4 av = *(const float4*)&A[(size_t)(tileM + r) * K + kc + cq * 4];
        *(float4*)&As[r][cq * 4] = av;
        if (TRANSB) {
            // W[n][k] -> Bs[k][n]
            float4 wv = *(const float4*)&B[(size_t)(tileN + r) * K + kc + cq * 4];
            Bs[cq * 4 + 0][r] = wv.x;
            Bs[cq * 4 + 1][r] = wv.y;
            Bs[cq * 4 + 2][r] = wv.z;
            Bs[cq * 4 + 3][r] = wv.w;
        } else {
            float4 bv = *(const float4*)&B[(size_t)(kc + r) * N + tileN + cq * 4];
            *(float4*)&Bs[r][cq * 4] = bv;
        }
        __syncthreads();
#pragma unroll
        for (int k = 0; k < 32; k++) {
            float a = As[r][k];
            float4 b4 = *(const float4*)&Bs[k][cq * 4];
            acc0 = fmaf(a, b4.x, acc0);
            acc1 = fmaf(a, b4.y, acc1);
            acc2 = fmaf(a, b4.z, acc2);
            acc3 = fmaf(a, b4.w, acc3);
        }
        __syncthreads();
    }
    int row = tileM + r, col = tileN + cq * 4;
    float4 o;
    o.x = acc0 * alpha; o.y = acc1 * alpha; o.z = acc2 * alpha; o.w = acc3 * alpha;
    if (BIAS) {
        float4 bv = *(const float4*)&bias[col];
        o.x += bv.x; o.y += bv.y; o.z += bv.z; o.w += bv.w;
    }
    if (RELU) {
        o.x = fmaxf(o.x, 0.f); o.y = fmaxf(o.y, 0.f);
        o.z = fmaxf(o.z, 0.f); o.w = fmaxf(o.w, 0.f);
    }
    if (RES) {
        float4 rv = *(const float4*)&res[(size_t)row * N + col];
        o.x += rv.x; o.y += rv.y; o.z += rv.z; o.w += rv.w;
    }
    *(float4*)&C[(size_t)row * N + col] = o;
}

// ---------------- streaming attention pass ----------------
// grid = (NCHUNK, BB), block = 64 (2 warps); thread owns g in [8*tid, 8*tid+8)
// Computes per-row: inline feature LN, dots (via qtw trick), softmax over 8 slots,
// then accumulates Upart[s][g] += (p_s+eps)*f_ln[g] and Z[s] += (p_s+eps).
__global__ void __launch_bounds__(64) attn_stream(
    const float* __restrict__ feats, const float* __restrict__ qt,
    const float* __restrict__ lnw, const float* __restrict__ lnb,
    float* __restrict__ Upart, float* __restrict__ Zpart,
    float* __restrict__ attn_out, int writeAttn) {
    const int b = blockIdx.y, chunk = blockIdx.x;
    const int tid = threadIdx.x;
    const int lane = tid & 31, wp = tid >> 5;
    const int g0 = tid * 8;

    __shared__ float red[2][2][12];
    __shared__ float red0[2][16];

    float wf[8], bf[8];
    *(float4*)&wf[0] = *(const float4*)&lnw[g0];
    *(float4*)&wf[4] = *(const float4*)&lnw[g0 + 4];
    *(float4*)&bf[0] = *(const float4*)&lnb[g0];
    *(float4*)&bf[4] = *(const float4*)&lnb[g0 + 4];

    float qtw[8][8], cb[8], qws[8];
#pragma unroll
    for (int s = 0; s < 8; s++) {
        float4 qa = *(const float4*)&qt[((size_t)b * 8 + s) * DD + g0];
        float4 qb = *(const float4*)&qt[((size_t)b * 8 + s) * DD + g0 + 4];
        float q[8] = {qa.x, qa.y, qa.z, qa.w, qb.x, qb.y, qb.z, qb.w};
        float cbp = 0.f, qp = 0.f;
#pragma unroll
        for (int j = 0; j < 8; j++) {
            qtw[s][j] = q[j] * wf[j];
            cbp = fmaf(q[j], bf[j], cbp);
            qp += qtw[s][j];
        }
        cb[s] = cbp; qws[s] = qp;
    }
#pragma unroll
    for (int s = 0; s < 8; s++) { cb[s] = wred(cb[s]); qws[s] = wred(qws[s]); }
    if (lane == 0) {
        *(float4*)&red0[wp][0]  = make_float4(cb[0], cb[1], cb[2], cb[3]);
        *(float4*)&red0[wp][4]  = make_float4(cb[4], cb[5], cb[6], cb[7]);
        *(float4*)&red0[wp][8]  = make_float4(qws[0], qws[1], qws[2], qws[3]);
        *(float4*)&red0[wp][12] = make_float4(qws[4], qws[5], qws[6], qws[7]);
    }
    __syncthreads();
#pragma unroll
    for (int s = 0; s < 8; s++) {
        cb[s]  = red0[0][s]     + red0[1][s];
        qws[s] = red0[0][8 + s] + red0[1][8 + s];
    }
    __syncthreads();

    float acc[8][8];
#pragma unroll
    for (int s = 0; s < 8; s++)
#pragma unroll
        for (int j = 0; j < 8; j++) acc[s][j] = 0.f;
    float zacc[8] = {0.f, 0.f, 0.f, 0.f, 0.f, 0.f, 0.f, 0.f};

    const float* fp = feats + ((size_t)b * FF + (size_t)chunk * ROWS_PER_CHUNK) * DD + g0;
    float4 xa = *(const float4*)fp;
    float4 xb = *(const float4*)(fp + 4);
    int par = 0;

    for (int r = 0; r < ROWS_PER_CHUNK; r++) {
        float x[8] = {xa.x, xa.y, xa.z, xa.w, xb.x, xb.y, xb.z, xb.w};
        if (r + 1 < ROWS_PER_CHUNK) {
            const float* np = fp + (size_t)(r + 1) * DD;
            xa = *(const float4*)np;
            xb = *(const float4*)(np + 4);
        }
        float s1 = 0.f, s2 = 0.f;
        float P[8] = {0.f, 0.f, 0.f, 0.f, 0.f, 0.f, 0.f, 0.f};
#pragma unroll
        for (int j = 0; j < 8; j++) {
            s1 += x[j];
            s2 = fmaf(x[j], x[j], s2);
#pragma unroll
            for (int s = 0; s < 8; s++) P[s] = fmaf(qtw[s][j], x[j], P[s]);
        }
        s1 = wred(s1); s2 = wred(s2);
#pragma unroll
        for (int s = 0; s < 8; s++) P[s] = wred(P[s]);
        if (lane == 0) {
            *(float4*)&red[par][wp][0] = make_float4(s1, s2, P[0], P[1]);
            *(float4*)&red[par][wp][4] = make_float4(P[2], P[3], P[4], P[5]);
            *(float2*)&red[par][wp][8] = make_float2(P[6], P[7]);
        }
        __syncthreads();
        {
            float4 a0 = *(const float4*)&red[par][0][0];
            float4 a1v = *(const float4*)&red[par][0][4];
            float2 a2 = *(const float2*)&red[par][0][8];
            float4 b0 = *(const float4*)&red[par][1][0];
            float4 b1v = *(const float4*)&red[par][1][4];
            float2 b2 = *(const float2*)&red[par][1][8];
            s1 = a0.x + b0.x; s2 = a0.y + b0.y;
            P[0] = a0.z + b0.z;  P[1] = a0.w + b0.w;
            P[2] = a1v.x + b1v.x; P[3] = a1v.y + b1v.y;
            P[4] = a1v.z + b1v.z; P[5] = a1v.w + b1v.w;
            P[6] = a2.x + b2.x;  P[7] = a2.y + b2.y;
        }
        par ^= 1;
        float m = s1 * (1.0f / DD);
        float var = s2 * (1.0f / DD) - m * m;
        float rstd = rsqrtf(var + LN_EPS);
        float mr = m * rstd;
        float d[8];
#pragma unroll
        for (int s = 0; s < 8; s++) {
            float t = fmaf(-mr, qws[s], cb[s]);
            d[s] = fmaf(rstd, P[s], t);
        }
        float mx = d[0];
#pragma unroll
        for (int s = 1; s < 8; s++) mx = fmaxf(mx, d[s]);
        float e[8]; float se = 0.f;
#pragma unroll
        for (int s = 0; s < 8; s++) { e[s] = __expf(d[s] - mx); se += e[s]; }
        float inv = 1.0f / se;
        float pe[8];
#pragma unroll
        for (int s = 0; s < 8; s++) {
            float p = e[s] * inv;
            pe[s] = p + ATTN_EPS;
            zacc[s] += pe[s];
        }
        if (writeAttn && wp == 0) {
            int f = chunk * ROWS_PER_CHUNK + r;
            float* ap = attn_out + (size_t)b * SS * FF + f;
            if (tid == 0) ap[0 * FF] = e[0] * inv;
            if (tid == 1) ap[1 * FF] = e[1] * inv;
            if (tid == 2) ap[2 * FF] = e[2] * inv;
            if (tid == 3) ap[3 * FF] = e[3] * inv;
            if (tid == 4) ap[4 * FF] = e[4] * inv;
            if (tid == 5) ap[5 * FF] = e[5] * inv;
            if (tid == 6) ap[6 * FF] = e[6] * inv;
            if (tid == 7) ap[7 * FF] = e[7] * inv;
        }
#pragma unroll
        for (int j = 0; j < 8; j++) {
            float aw = rstd * wf[j];
            float off = fmaf(-mr, wf[j], bf[j]);
            float xn = fmaf(aw, x[j], off);
#pragma unroll
            for (int s = 0; s < 8; s++) acc[s][j] = fmaf(pe[s], xn, acc[s][j]);
        }
    }

    float* up = Upart + (((size_t)b * NCHUNK + chunk) * SS) * DD + g0;
#pragma unroll
    for (int s = 0; s < 8; s++) {
        *(float4*)&up[(size_t)s * DD]     = make_float4(acc[s][0], acc[s][1], acc[s][2], acc[s][3]);
        *(float4*)&up[(size_t)s * DD + 4] = make_float4(acc[s][4], acc[s][5], acc[s][6], acc[s][7]);
    }
    if (tid == 0) {
        float* zp = Zpart + ((size_t)b * NCHUNK + chunk) * SS;
#pragma unroll
        for (int s = 0; s < 8; s++) zp[s] = zacc[s];
    }
}

// ---------------- reduce partials and normalize ----------------
// grid = 256 (b*8+s), block = 128: un[bs][g] = (sum_c Upart)/ (sum_c Zpart)
__global__ void reduce_u(const float* __restrict__ Upart, const float* __restrict__ Zpart,
                         float* __restrict__ Uo) {
    int bs = blockIdx.x;
    int b = bs >> 3, s = bs & 7;
    int tid = threadIdx.x;
    float4 acc = make_float4(0.f, 0.f, 0.f, 0.f);
    float z = 0.f;
    for (int c = 0; c < NCHUNK; c++) {
        const float* up = Upart + (((size_t)b * NCHUNK + c) * SS + s) * DD;
        float4 v = *(const float4*)&up[tid * 4];
        acc.x += v.x; acc.y += v.y; acc.z += v.z; acc.w += v.w;
        z += Zpart[((size_t)b * NCHUNK + c) * SS + s];
    }
    float inv = 1.0f / z;
    acc.x *= inv; acc.y *= inv; acc.z *= inv; acc.w *= inv;
    *(float4*)&Uo[(size_t)bs * DD + tid * 4] = acc;
}

// ---------------- GRU elementwise combine ----------------
// grid = 128, block = 256, float4 per thread over 256x512
__global__ void gru_combine(const float* __restrict__ gi, const float* __restrict__ gh,
                            const float* __restrict__ sn, float* __restrict__ out) {
    int i = blockIdx.x * blockDim.x + threadIdx.x;
    int i4 = i * 4;
    int row = i4 >> 9;
    int dcol = i4 & 511;
    size_t base = (size_t)row * (3 * DD) + dcol;
    float4 ir = *(const float4*)&gi[base];
    float4 iz = *(const float4*)&gi[base + DD];
    float4 in_ = *(const float4*)&gi[base + 2 * DD];
    float4 hr = *(const float4*)&gh[base];
    float4 hz = *(const float4*)&gh[base + DD];
    float4 hn = *(const float4*)&gh[base + 2 * DD];
    float4 h = *(const float4*)&sn[(size_t)row * DD + dcol];
    float4 o;
#define GRU1(c) { \
        float r_ = 1.0f / (1.0f + __expf(-(ir.c + hr.c))); \
        float z_ = 1.0f / (1.0f + __expf(-(iz.c + hz.c))); \
        float n_ = tanhf(in_.c + r_ * hn.c); \
        o.c = (1.0f - z_) * n_ + z_ * h.c; }
    GRU1(x) GRU1(y) GRU1(z) GRU1(w)
#undef GRU1
    *(float4*)&out[(size_t)row * DD + dcol] = o;
}

// ---------------- launch ----------------
extern "C" void kernel_launch(void* const* d_in, const int* in_sizes, int n_in,
                              void* d_out, int out_size) {
    const float* slots    = (const float*)d_in[0];
    const float* features = (const float*)d_in[1];
    const float* w_k      = (const float*)d_in[2];
    const float* w_v      = (const float*)d_in[3];
    const float* w_q      = (const float*)d_in[4];
    const float* ln_feat_w = (const float*)d_in[5];
    const float* ln_feat_b = (const float*)d_in[6];
    const float* ln_slot_w = (const float*)d_in[7];
    const float* ln_slot_b = (const float*)d_in[8];
    const float* gru_w_ih = (const float*)d_in[9];
    const float* gru_w_hh = (const float*)d_in[10];
    const float* gru_b_ih = (const float*)d_in[11];
    const float* gru_b_hh = (const float*)d_in[12];
    const float* ln_mlp_w = (const float*)d_in[13];
    const float* ln_mlp_b = (const float*)d_in[14];
    const float* mlp_w1   = (const float*)d_in[15];
    const float* mlp_b1   = (const float*)d_in[16];
    const float* mlp_w2   = (const float*)d_in[17];
    const float* mlp_b2   = (const float*)d_in[18];

    float *wqk, *cur, *sn, *qt, *Up, *Zp, *un, *upd, *gi, *gh, *hbuf, *a1;
    cudaGetSymbolAddress((void**)&wqk, g_wqk);
    cudaGetSymbolAddress((void**)&cur, g_cur);
    cudaGetSymbolAddress((void**)&sn,  g_sn);
    cudaGetSymbolAddress((void**)&qt,  g_qt);
    cudaGetSymbolAddress((void**)&Up,  g_Up);
    cudaGetSymbolAddress((void**)&Zp,  g_Zp);
    cudaGetSymbolAddress((void**)&un,  g_un);
    cudaGetSymbolAddress((void**)&upd, g_upd);
    cudaGetSymbolAddress((void**)&gi,  g_gi);
    cudaGetSymbolAddress((void**)&gh,  g_gh);
    cudaGetSymbolAddress((void**)&hbuf, g_h);
    cudaGetSymbolAddress((void**)&a1,  g_a1);

    float* out = (float*)d_out;                 // slots [32,8,512]
    float* out_attn = out + BB * SS * DD;       // pre_norm_attn [32,8,4096]

    cudaMemcpyAsync(cur, slots, (size_t)BB * SS * DD * sizeof(float),
                    cudaMemcpyDeviceToDevice, 0);

    // wqk = SCALE * w_q @ w_k^T   (TRANSB with W = w_k)
    gemm32<true, false, false, false><<<dim3(16, 16), 256>>>(
        w_q, w_k, nullptr, nullptr, wqk, DD, DD, DD, SCALE_QK);

    for (int it = 0; it < 3; it++) {
        ln_rows<<<BB * SS, 128>>>(cur, ln_slot_w, ln_slot_b, sn);
        gemm32<false, false, false, false><<<dim3(16, 8), 256>>>(
            sn, wqk, nullptr, nullptr, qt, BB * SS, DD, DD, 1.0f);
        attn_stream<<<dim3(NCHUNK, BB), 64>>>(
            features, qt, ln_feat_w, ln_feat_b, Up, Zp, out_attn, it == 2 ? 1 : 0);
        reduce_u<<<BB * SS, 128>>>(Up, Zp, un);
        gemm32<false, false, false, false><<<dim3(16, 8), 256>>>(
            un, w_v, nullptr, nullptr, upd, BB * SS, DD, DD, 1.0f);
        gemm32<true, true, false, false><<<dim3(48, 8), 256>>>(
            upd, gru_w_ih, gru_b_ih, nullptr, gi, BB * SS, 3 * DD, DD, 1.0f);
        gemm32<true, true, false, false><<<dim3(48, 8), 256>>>(
            sn, gru_w_hh, gru_b_hh, nullptr, gh, BB * SS, 3 * DD, DD, 1.0f);
        gru_combine<<<128, 256>>>(gi, gh, sn, cur);
        ln_rows<<<BB * SS, 128>>>(cur, ln_mlp_w, ln_mlp_b, hbuf);
        gemm32<false, true, true, false><<<dim3(64, 8), 256>>>(
            hbuf, mlp_w1, mlp_b1, nullptr, a1, BB * SS, HH, DD, 1.0f);
        float* dst = (it == 2) ? out : cur;
        gemm32<false, true, false, true><<<dim3(16, 8), 256>>>(
            a1, mlp_w2, mlp_b2, cur, dst, BB * SS, DD, HH, 1.0f);
    }
}

// round 8
// speedup vs baseline: 1.1153x; 1.1153x over previous
#include <cuda_runtime.h>
#include <cuda_bf16.h>
#include <math.h>

// Shapes
#define BB 32
#define FF 4096
#define SS 8
#define DD 512
#define HH 2048
#define NCHUNK 32
#define RPC (FF / NCHUNK)   // 128 rows per chunk
#define SCALE_QK 0.044194173824159216f
#define LN_EPS 1e-5f
#define ATTN_EPS 1e-8f

typedef unsigned long long u64;

// ---------------- scratch ----------------
__device__ float g_wqk [DD * DD];
__device__ float g_wkT [DD * DD];
__device__ float g_ihT [DD * 3 * DD];
__device__ float g_hhT [DD * 3 * DD];
__device__ float g_cur [BB * SS * DD];
__device__ float g_sn  [BB * SS * DD];
__device__ float g_qt  [BB * SS * DD];
__device__ float g_Up  [BB * NCHUNK * SS * DD];
__device__ float g_Zp  [BB * NCHUNK * SS];
__device__ float g_un  [BB * SS * DD];
__device__ float g_upd [BB * SS * DD];
__device__ float g_gi  [BB * SS * 3 * DD];
__device__ float g_gh  [BB * SS * 3 * DD];
__device__ float g_h   [BB * SS * DD];
__device__ float g_a1  [BB * SS * HH];

// ---------------- helpers ----------------
__device__ __forceinline__ float wred(float v) {
    v += __shfl_xor_sync(0xffffffffu, v, 16);
    v += __shfl_xor_sync(0xffffffffu, v, 8);
    v += __shfl_xor_sync(0xffffffffu, v, 4);
    v += __shfl_xor_sync(0xffffffffu, v, 2);
    v += __shfl_xor_sync(0xffffffffu, v, 1);
    return v;
}
__device__ __forceinline__ u64 pack2(float lo, float hi) {
    u64 r; asm("mov.b64 %0, {%1,%2};" : "=l"(r) : "f"(lo), "f"(hi)); return r;
}
__device__ __forceinline__ float2 u2f(u64 v) {
    float2 r; asm("mov.b64 {%0,%1}, %2;" : "=f"(r.x), "=f"(r.y) : "l"(v)); return r;
}
__device__ __forceinline__ u64 ffma2(u64 a, u64 b, u64 c) {
    u64 d; asm("fma.rn.f32x2 %0, %1, %2, %3;" : "=l"(d) : "l"(a), "l"(b), "l"(c)); return d;
}
__device__ __forceinline__ u64 fmul2(u64 a, u64 b) {
    u64 d; asm("mul.rn.f32x2 %0, %1, %2;" : "=l"(d) : "l"(a), "l"(b)); return d;
}
__device__ __forceinline__ u64 fadd2(u64 a, u64 b) {
    u64 d; asm("add.rn.f32x2 %0, %1, %2;" : "=l"(d) : "l"(a), "l"(b)); return d;
}

// ---------------- transpose (32x32 tiles, block 32x8) ----------------
__global__ void transpose_k(const float* __restrict__ A, float* __restrict__ At,
                            int R, int C) {
    __shared__ float t[32][33];
    int rb = blockIdx.y * 32, cb = blockIdx.x * 32;
    int tx = threadIdx.x, ty = threadIdx.y;
#pragma unroll
    for (int i = 0; i < 4; i++)
        t[ty + 8 * i][tx] = A[(size_t)(rb + ty + 8 * i) * C + cb + tx];
    __syncthreads();
#pragma unroll
    for (int i = 0; i < 4; i++)
        At[(size_t)(cb + ty + 8 * i) * R + rb + tx] = t[tx][ty + 8 * i];
}

// ---------------- LayerNorm rows of width 512 ----------------
__global__ void ln_rows(const float* __restrict__ X, const float* __restrict__ w,
                        const float* __restrict__ b, float* __restrict__ Y) {
    int row = blockIdx.x;
    int tid = threadIdx.x;
    const float* x = X + (size_t)row * DD;
    float4 v = *(const float4*)&x[tid * 4];
    float s1 = v.x + v.y + v.z + v.w;
    float s2 = v.x * v.x + v.y * v.y + v.z * v.z + v.w * v.w;
    s1 = wred(s1); s2 = wred(s2);
    __shared__ float sm[8];
    int lane = tid & 31, wp = tid >> 5;
    if (lane == 0) { sm[wp] = s1; sm[4 + wp] = s2; }
    __syncthreads();
    float st  = sm[0] + sm[1] + sm[2] + sm[3];
    float s2t = sm[4] + sm[5] + sm[6] + sm[7];
    float m = st * (1.0f / DD);
    float var = s2t * (1.0f / DD) - m * m;
    float rstd = rsqrtf(var + LN_EPS);
    float4 wv = *(const float4*)&w[tid * 4];
    float4 bv = *(const float4*)&b[tid * 4];
    float4 o;
    o.x = (v.x - m) * rstd * wv.x + bv.x;
    o.y = (v.y - m) * rstd * wv.y + bv.y;
    o.z = (v.z - m) * rstd * wv.z + bv.z;
    o.w = (v.w - m) * rstd * wv.w + bv.w;
    *(float4*)&Y[(size_t)row * DD + tid * 4] = o;
}

// ---------------- register-tiled NN GEMM ----------------
// C[M,N] = alpha*A[M,K]@B[K,N] (+bias)(+relu)(+res). TN=64, RN=4, block 128.
template<int TM, int RM, bool BIAS, bool RELU, bool RES>
__global__ void __launch_bounds__(128) gemm_rt(
    const float* __restrict__ A, const float* __restrict__ B,
    const float* __restrict__ bias, const float* __restrict__ res,
    float* __restrict__ C, int M, int N, int K, float alpha) {
    constexpr int ASTR = (RM == 4) ? 36 : 20;
    __shared__ float As[32][ASTR];
    __shared__ float Bs[32][64];
    int tid = threadIdx.x;
    int tx = tid & 15;      // n group (cols tx*4..+3)
    int ty = tid >> 4;      // m group (rows ty*RM..+RM-1)
    int tileM = blockIdx.y * TM;
    int tileN = blockIdx.x * 64;
    float acc[RM][4];
#pragma unroll
    for (int i = 0; i < RM; i++)
#pragma unroll
        for (int j = 0; j < 4; j++) acc[i][j] = 0.f;

    for (int kc = 0; kc < K; kc += 32) {
        // stage A (TM x 32), transposed into As[k][m]
#pragma unroll
        for (int i = 0; i < TM / 16; i++) {
            int f = tid + 128 * i;
            int m = f >> 3;
            int k4 = (f & 7) * 4;
            float4 v = *(const float4*)&A[(size_t)(tileM + m) * K + kc + k4];
            As[k4 + 0][m] = v.x;
            As[k4 + 1][m] = v.y;
            As[k4 + 2][m] = v.z;
            As[k4 + 3][m] = v.w;
        }
        // stage B (32 x 64)
#pragma unroll
        for (int i = 0; i < 4; i++) {
            int f = tid + 128 * i;
            int k = f >> 4;
            int n4 = (f & 15) * 4;
            *(float4*)&Bs[k][n4] = *(const float4*)&B[(size_t)(kc + k) * N + tileN + n4];
        }
        __syncthreads();
#pragma unroll
        for (int k = 0; k < 32; k++) {
            float a[RM];
            if (RM == 4) {
                float4 av = *(const float4*)&As[k][ty * 4];
                a[0] = av.x; a[1] = av.y; a[2] = av.z; a[3] = av.w;
            } else {
                float2 av = *(const float2*)&As[k][ty * 2];
                a[0] = av.x; a[1] = av.y;
            }
            float4 b4 = *(const float4*)&Bs[k][tx * 4];
#pragma unroll
            for (int i = 0; i < RM; i++) {
                acc[i][0] = fmaf(a[i], b4.x, acc[i][0]);
                acc[i][1] = fmaf(a[i], b4.y, acc[i][1]);
                acc[i][2] = fmaf(a[i], b4.z, acc[i][2]);
                acc[i][3] = fmaf(a[i], b4.w, acc[i][3]);
            }
        }
        __syncthreads();
    }
    int col = tileN + tx * 4;
    float4 bv = make_float4(0.f, 0.f, 0.f, 0.f);
    if (BIAS) bv = *(const float4*)&bias[col];
#pragma unroll
    for (int i = 0; i < RM; i++) {
        int row = tileM + ty * RM + i;
        float4 o;
        o.x = acc[i][0] * alpha; o.y = acc[i][1] * alpha;
        o.z = acc[i][2] * alpha; o.w = acc[i][3] * alpha;
        if (BIAS) { o.x += bv.x; o.y += bv.y; o.z += bv.z; o.w += bv.w; }
        if (RELU) {
            o.x = fmaxf(o.x, 0.f); o.y = fmaxf(o.y, 0.f);
            o.z = fmaxf(o.z, 0.f); o.w = fmaxf(o.w, 0.f);
        }
        if (RES) {
            float4 rv = *(const float4*)&res[(size_t)row * N + col];
            o.x += rv.x; o.y += rv.y; o.z += rv.z; o.w += rv.w;
        }
        *(float4*)&C[(size_t)row * N + col] = o;
    }
}

// ---------------- streaming attention pass (f32x2 packed) ----------------
// grid (NCHUNK, BB), block 64. Thread owns j in [8*tid, 8*tid+8).
// Accumulates A1=Σ pe·rstd·x, t1=Σ pe·m·rstd, z=Σ pe; wf/bf applied in epilogue.
__global__ void __launch_bounds__(64) attn_stream(
    const float* __restrict__ feats, const float* __restrict__ qt,
    const float* __restrict__ lnw, const float* __restrict__ lnb,
    float* __restrict__ Upart, float* __restrict__ Zpart,
    float* __restrict__ attn_out, int writeAttn) {
    const int b = blockIdx.y, chunk = blockIdx.x;
    const int tid = threadIdx.x;
    const int lane = tid & 31, wp = tid >> 5;
    const int g0 = tid * 8;

    __shared__ float red[2][2][16];
    __shared__ float red0[2][16];

    float wf[8], bf[8];
    *(float4*)&wf[0] = *(const float4*)&lnw[g0];
    *(float4*)&wf[4] = *(const float4*)&lnw[g0 + 4];
    *(float4*)&bf[0] = *(const float4*)&lnb[g0];
    *(float4*)&bf[4] = *(const float4*)&lnb[g0 + 4];

    u64 qtw2[8][4];
    float cb[8], qws[8];
#pragma unroll
    for (int s = 0; s < 8; s++) {
        float q[8];
        *(float4*)&q[0] = *(const float4*)&qt[((size_t)b * 8 + s) * DD + g0];
        *(float4*)&q[4] = *(const float4*)&qt[((size_t)b * 8 + s) * DD + g0 + 4];
        float cbp = 0.f, qp = 0.f, w[8];
#pragma unroll
        for (int j = 0; j < 8; j++) {
            w[j] = q[j] * wf[j];
            cbp = fmaf(q[j], bf[j], cbp);
            qp += w[j];
        }
        qtw2[s][0] = pack2(w[0], w[1]);
        qtw2[s][1] = pack2(w[2], w[3]);
        qtw2[s][2] = pack2(w[4], w[5]);
        qtw2[s][3] = pack2(w[6], w[7]);
        cb[s] = cbp; qws[s] = qp;
    }
#pragma unroll
    for (int s = 0; s < 8; s++) { cb[s] = wred(cb[s]); qws[s] = wred(qws[s]); }
    if (lane == 0) {
        *(float4*)&red0[wp][0]  = make_float4(cb[0], cb[1], cb[2], cb[3]);
        *(float4*)&red0[wp][4]  = make_float4(cb[4], cb[5], cb[6], cb[7]);
        *(float4*)&red0[wp][8]  = make_float4(qws[0], qws[1], qws[2], qws[3]);
        *(float4*)&red0[wp][12] = make_float4(qws[4], qws[5], qws[6], qws[7]);
    }
    __syncthreads();
#pragma unroll
    for (int s = 0; s < 8; s++) {
        cb[s]  = red0[0][s]     + red0[1][s];
        qws[s] = red0[0][8 + s] + red0[1][8 + s];
    }
    __syncthreads();

    u64 acc2[8][4];
#pragma unroll
    for (int s = 0; s < 8; s++)
#pragma unroll
        for (int q = 0; q < 4; q++) acc2[s][q] = 0ull;
    float zacc[8]  = {0.f, 0.f, 0.f, 0.f, 0.f, 0.f, 0.f, 0.f};
    float t1acc[8] = {0.f, 0.f, 0.f, 0.f, 0.f, 0.f, 0.f, 0.f};

    const float* fp = feats + ((size_t)b * FF + (size_t)chunk * RPC) * DD + g0;
    ulonglong2 xa = *(const ulonglong2*)fp;
    ulonglong2 xb = *(const ulonglong2*)(fp + 4);
    int par = 0;

    for (int r = 0; r < RPC; r++) {
        u64 x2[4] = {xa.x, xa.y, xb.x, xb.y};
        if (r + 1 < RPC) {
            const float* np = fp + (size_t)(r + 1) * DD;
            xa = *(const ulonglong2*)np;
            xb = *(const ulonglong2*)(np + 4);
        }
        // packed partial sums
        u64 sa = fadd2(fadd2(x2[0], x2[1]), fadd2(x2[2], x2[3]));
        u64 sb = ffma2(x2[3], x2[3], ffma2(x2[2], x2[2],
                 ffma2(x2[1], x2[1], fmul2(x2[0], x2[0]))));
        u64 P2[8];
#pragma unroll
        for (int s = 0; s < 8; s++)
            P2[s] = ffma2(x2[3], qtw2[s][3], ffma2(x2[2], qtw2[s][2],
                    ffma2(x2[1], qtw2[s][1], fmul2(x2[0], qtw2[s][0]))));
        float2 fa = u2f(sa); float s1 = fa.x + fa.y;
        float2 fb = u2f(sb); float s2 = fb.x + fb.y;
        float P[8];
#pragma unroll
        for (int s = 0; s < 8; s++) { float2 t = u2f(P2[s]); P[s] = t.x + t.y; }
        s1 = wred(s1); s2 = wred(s2);
#pragma unroll
        for (int s = 0; s < 8; s++) P[s] = wred(P[s]);
        if (lane == 0) {
            *(float4*)&red[par][wp][0] = make_float4(s1, s2, P[0], P[1]);
            *(float4*)&red[par][wp][4] = make_float4(P[2], P[3], P[4], P[5]);
            *(float4*)&red[par][wp][8] = make_float4(P[6], P[7], 0.f, 0.f);
        }
        __syncthreads();
        {
            float4 a0 = *(const float4*)&red[par][0][0];
            float4 a1v = *(const float4*)&red[par][0][4];
            float4 a2 = *(const float4*)&red[par][0][8];
            float4 b0 = *(const float4*)&red[par][1][0];
            float4 b1v = *(const float4*)&red[par][1][4];
            float4 b2 = *(const float4*)&red[par][1][8];
            s1 = a0.x + b0.x; s2 = a0.y + b0.y;
            P[0] = a0.z + b0.z;  P[1] = a0.w + b0.w;
            P[2] = a1v.x + b1v.x; P[3] = a1v.y + b1v.y;
            P[4] = a1v.z + b1v.z; P[5] = a1v.w + b1v.w;
            P[6] = a2.x + b2.x;  P[7] = a2.y + b2.y;
        }
        par ^= 1;
        float m = s1 * (1.0f / DD);
        float var = s2 * (1.0f / DD) - m * m;
        float rstd = rsqrtf(var + LN_EPS);
        float mr = m * rstd;
        float d[8];
#pragma unroll
        for (int s = 0; s < 8; s++)
            d[s] = fmaf(rstd, P[s], fmaf(-mr, qws[s], cb[s]));
        float mx = d[0];
#pragma unroll
        for (int s = 1; s < 8; s++) mx = fmaxf(mx, d[s]);
        float e[8]; float se = 0.f;
#pragma unroll
        for (int s = 0; s < 8; s++) { e[s] = __expf(d[s] - mx); se += e[s]; }
        float inv = 1.0f / se;
        float pe[8];
#pragma unroll
        for (int s = 0; s < 8; s++) {
            float p = e[s] * inv;
            pe[s] = p + ATTN_EPS;
            zacc[s] += pe[s];
            t1acc[s] = fmaf(pe[s], mr, t1acc[s]);
        }
        if (writeAttn && wp == 0) {
            int f = chunk * RPC + r;
            float* ap = attn_out + (size_t)b * SS * FF + f;
            if (tid == 0) ap[0 * FF] = e[0] * inv;
            if (tid == 1) ap[1 * FF] = e[1] * inv;
            if (tid == 2) ap[2 * FF] = e[2] * inv;
            if (tid == 3) ap[3 * FF] = e[3] * inv;
            if (tid == 4) ap[4 * FF] = e[4] * inv;
            if (tid == 5) ap[5 * FF] = e[5] * inv;
            if (tid == 6) ap[6 * FF] = e[6] * inv;
            if (tid == 7) ap[7 * FF] = e[7] * inv;
        }
#pragma unroll
        for (int s = 0; s < 8; s++) {
            float pr = pe[s] * rstd;
            u64 pr2 = pack2(pr, pr);
            acc2[s][0] = ffma2(pr2, x2[0], acc2[s][0]);
            acc2[s][1] = ffma2(pr2, x2[1], acc2[s][1]);
            acc2[s][2] = ffma2(pr2, x2[2], acc2[s][2]);
            acc2[s][3] = ffma2(pr2, x2[3], acc2[s][3]);
        }
    }

    // epilogue: U[s][j] = wf[j]*(A1[s][j] - t1[s]) + bf[j]*z[s]
    float* up = Upart + (((size_t)b * NCHUNK + chunk) * SS) * DD + g0;
#pragma unroll
    for (int s = 0; s < 8; s++) {
        float tt = t1acc[s], zz = zacc[s];
        float o[8];
#pragma unroll
        for (int q = 0; q < 4; q++) {
            float2 av = u2f(acc2[s][q]);
            o[2 * q]     = fmaf(wf[2 * q],     av.x - tt, bf[2 * q] * zz);
            o[2 * q + 1] = fmaf(wf[2 * q + 1], av.y - tt, bf[2 * q + 1] * zz);
        }
        *(float4*)&up[(size_t)s * DD]     = *(float4*)&o[0];
        *(float4*)&up[(size_t)s * DD + 4] = *(float4*)&o[4];
    }
    if (tid == 0) {
        float* zp = Zpart + ((size_t)b * NCHUNK + chunk) * SS;
#pragma unroll
        for (int s = 0; s < 8; s++) zp[s] = zacc[s];
    }
}

// ---------------- reduce partials + normalize ----------------
__global__ void reduce_u(const float* __restrict__ Upart, const float* __restrict__ Zpart,
                         float* __restrict__ Uo) {
    int bs = blockIdx.x;
    int b = bs >> 3, s = bs & 7;
    int tid = threadIdx.x;
    float4 acc = make_float4(0.f, 0.f, 0.f, 0.f);
    float z = 0.f;
    for (int c = 0; c < NCHUNK; c++) {
        const float* up = Upart + (((size_t)b * NCHUNK + c) * SS + s) * DD;
        float4 v = *(const float4*)&up[tid * 4];
        acc.x += v.x; acc.y += v.y; acc.z += v.z; acc.w += v.w;
        z += Zpart[((size_t)b * NCHUNK + c) * SS + s];
    }
    float inv = 1.0f / z;
    acc.x *= inv; acc.y *= inv; acc.z *= inv; acc.w *= inv;
    *(float4*)&Uo[(size_t)bs * DD + tid * 4] = acc;
}

// ---------------- fused GRU combine + MLP LayerNorm ----------------
// grid 256 rows, block 128 (4 elems/thread). Writes cur (gru out) and hbuf (LN).
__global__ void __launch_bounds__(128) gru_ln(
    const float* __restrict__ gi, const float* __restrict__ gh,
    const float* __restrict__ sn, const float* __restrict__ lnw,
    const float* __restrict__ lnb, float* __restrict__ cur, float* __restrict__ hbuf) {
    int row = blockIdx.x;
    int tid = threadIdx.x;
    int dcol = tid * 4;
    size_t base = (size_t)row * (3 * DD) + dcol;
    float4 ir = *(const float4*)&gi[base];
    float4 iz = *(const float4*)&gi[base + DD];
    float4 in_ = *(const float4*)&gi[base + 2 * DD];
    float4 hr = *(const float4*)&gh[base];
    float4 hz = *(const float4*)&gh[base + DD];
    float4 hn = *(const float4*)&gh[base + 2 * DD];
    float4 h = *(const float4*)&sn[(size_t)row * DD + dcol];
    float4 o;
#define GRU1(c) { \
        float r_ = 1.0f / (1.0f + __expf(-(ir.c + hr.c))); \
        float z_ = 1.0f / (1.0f + __expf(-(iz.c + hz.c))); \
        float n_ = tanhf(in_.c + r_ * hn.c); \
        o.c = (1.0f - z_) * n_ + z_ * h.c; }
    GRU1(x) GRU1(y) GRU1(z) GRU1(w)
#undef GRU1
    *(float4*)&cur[(size_t)row * DD + dcol] = o;
    // LayerNorm over o
    float s1 = o.x + o.y + o.z + o.w;
    float s2 = o.x * o.x + o.y * o.y + o.z * o.z + o.w * o.w;
    s1 = wred(s1); s2 = wred(s2);
    __shared__ float sm[8];
    int lane = tid & 31, wp = tid >> 5;
    if (lane == 0) { sm[wp] = s1; sm[4 + wp] = s2; }
    __syncthreads();
    float st  = sm[0] + sm[1] + sm[2] + sm[3];
    float s2t = sm[4] + sm[5] + sm[6] + sm[7];
    float m = st * (1.0f / DD);
    float var = s2t * (1.0f / DD) - m * m;
    float rstd = rsqrtf(var + LN_EPS);
    float4 wv = *(const float4*)&lnw[dcol];
    float4 bv = *(const float4*)&lnb[dcol];
    float4 y;
    y.x = (o.x - m) * rstd * wv.x + bv.x;
    y.y = (o.y - m) * rstd * wv.y + bv.y;
    y.z = (o.z - m) * rstd * wv.z + bv.z;
    y.w = (o.w - m) * rstd * wv.w + bv.w;
    *(float4*)&hbuf[(size_t)row * DD + dcol] = y;
}

// ---------------- launch ----------------
extern "C" void kernel_launch(void* const* d_in, const int* in_sizes, int n_in,
                              void* d_out, int out_size) {
    const float* slots     = (const float*)d_in[0];
    const float* features  = (const float*)d_in[1];
    const float* w_k       = (const float*)d_in[2];
    const float* w_v       = (const float*)d_in[3];
    const float* w_q       = (const float*)d_in[4];
    const float* ln_feat_w = (const float*)d_in[5];
    const float* ln_feat_b = (const float*)d_in[6];
    const float* ln_slot_w = (const float*)d_in[7];
    const float* ln_slot_b = (const float*)d_in[8];
    const float* gru_w_ih  = (const float*)d_in[9];
    const float* gru_w_hh  = (const float*)d_in[10];
    const float* gru_b_ih  = (const float*)d_in[11];
    const float* gru_b_hh  = (const float*)d_in[12];
    const float* ln_mlp_w  = (const float*)d_in[13];
    const float* ln_mlp_b  = (const float*)d_in[14];
    const float* mlp_w1    = (const float*)d_in[15];
    const float* mlp_b1    = (const float*)d_in[16];
    const float* mlp_w2    = (const float*)d_in[17];
    const float* mlp_b2    = (const float*)d_in[18];

    float *wqk, *wkT, *ihT, *hhT, *cur, *sn, *qt, *Up, *Zp, *un, *upd, *gi, *gh, *hbuf, *a1;
    cudaGetSymbolAddress((void**)&wqk, g_wqk);
    cudaGetSymbolAddress((void**)&wkT, g_wkT);
    cudaGetSymbolAddress((void**)&ihT, g_ihT);
    cudaGetSymbolAddress((void**)&hhT, g_hhT);
    cudaGetSymbolAddress((void**)&cur, g_cur);
    cudaGetSymbolAddress((void**)&sn,  g_sn);
    cudaGetSymbolAddress((void**)&qt,  g_qt);
    cudaGetSymbolAddress((void**)&Up,  g_Up);
    cudaGetSymbolAddress((void**)&Zp,  g_Zp);
    cudaGetSymbolAddress((void**)&un,  g_un);
    cudaGetSymbolAddress((void**)&upd, g_upd);
    cudaGetSymbolAddress((void**)&gi,  g_gi);
    cudaGetSymbolAddress((void**)&gh,  g_gh);
    cudaGetSymbolAddress((void**)&hbuf, g_h);
    cudaGetSymbolAddress((void**)&a1,  g_a1);

    float* out = (float*)d_out;
    float* out_attn = out + BB * SS * DD;

    cudaMemcpyAsync(cur, slots, (size_t)BB * SS * DD * sizeof(float),
                    cudaMemcpyDeviceToDevice, 0);

    // prep: transposes + wqk
    transpose_k<<<dim3(16, 16), dim3(32, 8)>>>(w_k, wkT, DD, DD);
    transpose_k<<<dim3(16, 48), dim3(32, 8)>>>(gru_w_ih, ihT, 3 * DD, DD);
    transpose_k<<<dim3(16, 48), dim3(32, 8)>>>(gru_w_hh, hhT, 3 * DD, DD);
    // wqk = SCALE * w_q @ w_k^T  (NN with wkT)
    gemm_rt<32, 4, false, false, false><<<dim3(8, 16), 128>>>(
        w_q, wkT, nullptr, nullptr, wqk, DD, DD, DD, SCALE_QK);

    for (int it = 0; it < 3; it++) {
        ln_rows<<<BB * SS, 128>>>(cur, ln_slot_w, ln_slot_b, sn);
        gemm_rt<16, 2, false, false, false><<<dim3(8, 16), 128>>>(
            sn, wqk, nullptr, nullptr, qt, BB * SS, DD, DD, 1.0f);
        attn_stream<<<dim3(NCHUNK, BB), 64>>>(
            features, qt, ln_feat_w, ln_feat_b, Up, Zp, out_attn, it == 2 ? 1 : 0);
        reduce_u<<<BB * SS, 128>>>(Up, Zp, un);
        gemm_rt<16, 2, false, false, false><<<dim3(8, 16), 128>>>(
            un, w_v, nullptr, nullptr, upd, BB * SS, DD, DD, 1.0f);
        gemm_rt<32, 4, true, false, false><<<dim3(24, 8), 128>>>(
            upd, ihT, gru_b_ih, nullptr, gi, BB * SS, 3 * DD, DD, 1.0f);
        gemm_rt<32, 4, true, false, false><<<dim3(24, 8), 128>>>(
            sn, hhT, gru_b_hh, nullptr, gh, BB * SS, 3 * DD, DD, 1.0f);
        gru_ln<<<BB * SS, 128>>>(gi, gh, sn, ln_mlp_w, ln_mlp_b, cur, hbuf);
        gemm_rt<32, 4, true, true, false><<<dim3(32, 8), 128>>>(
            hbuf, mlp_w1, mlp_b1, nullptr, a1, BB * SS, HH, DD, 1.0f);
        float* dst = (it == 2) ? out : cur;
        gemm_rt<16, 2, true, false, true><<<dim3(8, 16), 128>>>(
            a1, mlp_w2, mlp_b2, cur, dst, BB * SS, DD, HH, 1.0f);
    }
}

// round 12
// speedup vs baseline: 1.3804x; 1.2377x over previous
#include <cuda_runtime.h>
#include <cuda_bf16.h>
#include <math.h>

// Shapes
#define BB 32
#define FF 4096
#define SS 8
#define DD 512
#define HH 2048
#define NCHUNK 32
#define RPC (FF / NCHUNK)   // 128 rows per chunk
#define SCALE_QK 0.044194173824159216f
#define LN_EPS 1e-5f
#define ATTN_EPS 1e-8f

typedef unsigned long long u64;

// ---------------- scratch ----------------
__device__ float g_wqk [DD * DD];
__device__ float g_wkT [DD * DD];
__device__ float g_ihT [DD * 3 * DD];
__device__ float g_hhT [DD * 3 * DD];
__device__ float g_cur [BB * SS * DD];
__device__ float g_sn  [BB * SS * DD];
__device__ float g_qt  [BB * SS * DD];
__device__ float g_Up  [BB * NCHUNK * SS * DD];
__device__ float g_Zp  [BB * NCHUNK * SS];
__device__ float g_un  [BB * SS * DD];
__device__ float g_upd [BB * SS * DD];
__device__ float g_gi  [BB * SS * 3 * DD];
__device__ float g_gh  [BB * SS * 3 * DD];
__device__ float g_h   [BB * SS * DD];
__device__ float g_a1  [BB * SS * HH];
__device__ float g_P   [2 * 1024 * 1024];   // split-K partials (8 MB)

// ---------------- helpers ----------------
__device__ __forceinline__ float wred(float v) {
    v += __shfl_xor_sync(0xffffffffu, v, 16);
    v += __shfl_xor_sync(0xffffffffu, v, 8);
    v += __shfl_xor_sync(0xffffffffu, v, 4);
    v += __shfl_xor_sync(0xffffffffu, v, 2);
    v += __shfl_xor_sync(0xffffffffu, v, 1);
    return v;
}
__device__ __forceinline__ u64 pack2(float lo, float hi) {
    u64 r; asm("mov.b64 %0, {%1,%2};" : "=l"(r) : "f"(lo), "f"(hi)); return r;
}
__device__ __forceinline__ float2 u2f(u64 v) {
    float2 r; asm("mov.b64 {%0,%1}, %2;" : "=f"(r.x), "=f"(r.y) : "l"(v)); return r;
}
__device__ __forceinline__ u64 ffma2(u64 a, u64 b, u64 c) {
    u64 d; asm("fma.rn.f32x2 %0, %1, %2, %3;" : "=l"(d) : "l"(a), "l"(b), "l"(c)); return d;
}
__device__ __forceinline__ u64 fmul2(u64 a, u64 b) {
    u64 d; asm("mul.rn.f32x2 %0, %1, %2;" : "=l"(d) : "l"(a), "l"(b)); return d;
}
__device__ __forceinline__ u64 fadd2(u64 a, u64 b) {
    u64 d; asm("add.rn.f32x2 %0, %1, %2;" : "=l"(d) : "l"(a), "l"(b)); return d;
}

// ---------------- transpose (32x32 tiles, block 32x8) ----------------
__global__ void transpose_k(const float* __restrict__ A, float* __restrict__ At,
                            int R, int C) {
    __shared__ float t[32][33];
    int rb = blockIdx.y * 32, cb = blockIdx.x * 32;
    int tx = threadIdx.x, ty = threadIdx.y;
#pragma unroll
    for (int i = 0; i < 4; i++)
        t[ty + 8 * i][tx] = A[(size_t)(rb + ty + 8 * i) * C + cb + tx];
    __syncthreads();
#pragma unroll
    for (int i = 0; i < 4; i++)
        At[(size_t)(cb + ty + 8 * i) * R + rb + tx] = t[tx][ty + 8 * i];
}

// ---------------- LayerNorm rows of width 512 ----------------
__global__ void ln_rows(const float* __restrict__ X, const float* __restrict__ w,
                        const float* __restrict__ b, float* __restrict__ Y) {
    int row = blockIdx.x;
    int tid = threadIdx.x;
    const float* x = X + (size_t)row * DD;
    float4 v = *(const float4*)&x[tid * 4];
    float s1 = v.x + v.y + v.z + v.w;
    float s2 = v.x * v.x + v.y * v.y + v.z * v.z + v.w * v.w;
    s1 = wred(s1); s2 = wred(s2);
    __shared__ float sm[8];
    int lane = tid & 31, wp = tid >> 5;
    if (lane == 0) { sm[wp] = s1; sm[4 + wp] = s2; }
    __syncthreads();
    float st  = sm[0] + sm[1] + sm[2] + sm[3];
    float s2t = sm[4] + sm[5] + sm[6] + sm[7];
    float m = st * (1.0f / DD);
    float var = s2t * (1.0f / DD) - m * m;
    float rstd = rsqrtf(var + LN_EPS);
    float4 wv = *(const float4*)&w[tid * 4];
    float4 bv = *(const float4*)&b[tid * 4];
    float4 o;
    o.x = (v.x - m) * rstd * wv.x + bv.x;
    o.y = (v.y - m) * rstd * wv.y + bv.y;
    o.z = (v.z - m) * rstd * wv.z + bv.z;
    o.w = (v.w - m) * rstd * wv.w + bv.w;
    *(float4*)&Y[(size_t)row * DD + tid * 4] = o;
}

// ---------------- split-K GEMM: partial P[z] = A[:, kz] @ B[kz, :] ----------------
// tile 32M x 64N, block 128. grid (N/64, M/32, NSPLIT), Kr = K/NSPLIT.
__global__ void __launch_bounds__(128) gemm_sk(
    const float* __restrict__ A, const float* __restrict__ B,
    float* __restrict__ P, int M, int N, int K, int Kr) {
    __shared__ float As[32][36];
    __shared__ float Bs[32][64];
    int tid = threadIdx.x;
    int tx = tid & 15;      // n group (cols tx*4..+3)
    int ty = tid >> 4;      // m group (rows ty*4..+3)
    int tileM = blockIdx.y * 32;
    int tileN = blockIdx.x * 64;
    int k0 = blockIdx.z * Kr;
    float acc[4][4];
#pragma unroll
    for (int i = 0; i < 4; i++)
#pragma unroll
        for (int j = 0; j < 4; j++) acc[i][j] = 0.f;

    for (int kc = k0; kc < k0 + Kr; kc += 32) {
        // stage A (32 x 32) transposed into As[k][m]
#pragma unroll
        for (int i = 0; i < 2; i++) {
            int f = tid + 128 * i;
            int m = f >> 3;
            int k4 = (f & 7) * 4;
            float4 v = *(const float4*)&A[(size_t)(tileM + m) * K + kc + k4];
            As[k4 + 0][m] = v.x;
            As[k4 + 1][m] = v.y;
            As[k4 + 2][m] = v.z;
            As[k4 + 3][m] = v.w;
        }
        // stage B (32 x 64)
#pragma unroll
        for (int i = 0; i < 4; i++) {
            int f = tid + 128 * i;
            int k = f >> 4;
            int n4 = (f & 15) * 4;
            *(float4*)&Bs[k][n4] = *(const float4*)&B[(size_t)(kc + k) * N + tileN + n4];
        }
        __syncthreads();
#pragma unroll
        for (int k = 0; k < 32; k++) {
            float4 av = *(const float4*)&As[k][ty * 4];
            float4 b4 = *(const float4*)&Bs[k][tx * 4];
            float a[4] = {av.x, av.y, av.z, av.w};
#pragma unroll
            for (int i = 0; i < 4; i++) {
                acc[i][0] = fmaf(a[i], b4.x, acc[i][0]);
                acc[i][1] = fmaf(a[i], b4.y, acc[i][1]);
                acc[i][2] = fmaf(a[i], b4.z, acc[i][2]);
                acc[i][3] = fmaf(a[i], b4.w, acc[i][3]);
            }
        }
        __syncthreads();
    }
    float* p = P + (size_t)blockIdx.z * M * N;
    int col = tileN + tx * 4;
#pragma unroll
    for (int i = 0; i < 4; i++) {
        int row = tileM + ty * 4 + i;
        *(float4*)&p[(size_t)row * N + col] =
            make_float4(acc[i][0], acc[i][1], acc[i][2], acc[i][3]);
    }
}

// ---------------- split-K reduce + epilogue ----------------
// block 256, grid = M*N/1024. C = alpha*sum_z P[z] (+bias)(+relu)(+res)
template<bool BIAS, bool RELU, bool RES>
__global__ void __launch_bounds__(256) reduce_c(
    const float* __restrict__ P, const float* __restrict__ bias,
    const float* __restrict__ res, float* __restrict__ C,
    int M, int N, int nsplit, float alpha) {
    int i4 = (blockIdx.x * 256 + threadIdx.x) * 4;
    size_t MN = (size_t)M * N;
    float4 acc = *(const float4*)&P[i4];
    for (int z = 1; z < nsplit; z++) {
        float4 v = *(const float4*)&P[(size_t)z * MN + i4];
        acc.x += v.x; acc.y += v.y; acc.z += v.z; acc.w += v.w;
    }
    acc.x *= alpha; acc.y *= alpha; acc.z *= alpha; acc.w *= alpha;
    if (BIAS) {
        int col = i4 % N;
        float4 bv = *(const float4*)&bias[col];
        acc.x += bv.x; acc.y += bv.y; acc.z += bv.z; acc.w += bv.w;
    }
    if (RELU) {
        acc.x = fmaxf(acc.x, 0.f); acc.y = fmaxf(acc.y, 0.f);
        acc.z = fmaxf(acc.z, 0.f); acc.w = fmaxf(acc.w, 0.f);
    }
    if (RES) {
        float4 rv = *(const float4*)&res[i4];
        acc.x += rv.x; acc.y += rv.y; acc.z += rv.z; acc.w += rv.w;
    }
    *(float4*)&C[i4] = acc;
}

// ---------------- streaming attention pass (f32x2 packed) ----------------
// grid (NCHUNK, BB), block 64. Thread owns j in [8*tid, 8*tid+8).
__global__ void __launch_bounds__(64) attn_stream(
    const float* __restrict__ feats, const float* __restrict__ qt,
    const float* __restrict__ lnw, const float* __restrict__ lnb,
    float* __restrict__ Upart, float* __restrict__ Zpart,
    float* __restrict__ attn_out, int writeAttn) {
    const int b = blockIdx.y, chunk = blockIdx.x;
    const int tid = threadIdx.x;
    const int lane = tid & 31, wp = tid >> 5;
    const int g0 = tid * 8;

    __shared__ float red[2][2][16];
    __shared__ float red0[2][16];

    float wf[8], bf[8];
    *(float4*)&wf[0] = *(const float4*)&lnw[g0];
    *(float4*)&wf[4] = *(const float4*)&lnw[g0 + 4];
    *(float4*)&bf[0] = *(const float4*)&lnb[g0];
    *(float4*)&bf[4] = *(const float4*)&lnb[g0 + 4];

    u64 qtw2[8][4];
    float cb[8], qws[8];
#pragma unroll
    for (int s = 0; s < 8; s++) {
        float q[8];
        *(float4*)&q[0] = *(const float4*)&qt[((size_t)b * 8 + s) * DD + g0];
        *(float4*)&q[4] = *(const float4*)&qt[((size_t)b * 8 + s) * DD + g0 + 4];
        float cbp = 0.f, qp = 0.f, w[8];
#pragma unroll
        for (int j = 0; j < 8; j++) {
            w[j] = q[j] * wf[j];
            cbp = fmaf(q[j], bf[j], cbp);
            qp += w[j];
        }
        qtw2[s][0] = pack2(w[0], w[1]);
        qtw2[s][1] = pack2(w[2], w[3]);
        qtw2[s][2] = pack2(w[4], w[5]);
        qtw2[s][3] = pack2(w[6], w[7]);
        cb[s] = cbp; qws[s] = qp;
    }
#pragma unroll
    for (int s = 0; s < 8; s++) { cb[s] = wred(cb[s]); qws[s] = wred(qws[s]); }
    if (lane == 0) {
        *(float4*)&red0[wp][0]  = make_float4(cb[0], cb[1], cb[2], cb[3]);
        *(float4*)&red0[wp][4]  = make_float4(cb[4], cb[5], cb[6], cb[7]);
        *(float4*)&red0[wp][8]  = make_float4(qws[0], qws[1], qws[2], qws[3]);
        *(float4*)&red0[wp][12] = make_float4(qws[4], qws[5], qws[6], qws[7]);
    }
    __syncthreads();
#pragma unroll
    for (int s = 0; s < 8; s++) {
        cb[s]  = red0[0][s]     + red0[1][s];
        qws[s] = red0[0][8 + s] + red0[1][8 + s];
    }
    __syncthreads();

    u64 acc2[8][4];
#pragma unroll
    for (int s = 0; s < 8; s++)
#pragma unroll
        for (int q = 0; q < 4; q++) acc2[s][q] = 0ull;
    float zacc[8]  = {0.f, 0.f, 0.f, 0.f, 0.f, 0.f, 0.f, 0.f};
    float t1acc[8] = {0.f, 0.f, 0.f, 0.f, 0.f, 0.f, 0.f, 0.f};

    const float* fp = feats + ((size_t)b * FF + (size_t)chunk * RPC) * DD + g0;
    ulonglong2 xa = *(const ulonglong2*)fp;
    ulonglong2 xb = *(const ulonglong2*)(fp + 4);
    int par = 0;

    for (int r = 0; r < RPC; r++) {
        u64 x2[4] = {xa.x, xa.y, xb.x, xb.y};
        if (r + 1 < RPC) {
            const float* np = fp + (size_t)(r + 1) * DD;
            xa = *(const ulonglong2*)np;
            xb = *(const ulonglong2*)(np + 4);
        }
        u64 sa = fadd2(fadd2(x2[0], x2[1]), fadd2(x2[2], x2[3]));
        u64 sb = ffma2(x2[3], x2[3], ffma2(x2[2], x2[2],
                 ffma2(x2[1], x2[1], fmul2(x2[0], x2[0]))));
        u64 P2[8];
#pragma unroll
        for (int s = 0; s < 8; s++)
            P2[s] = ffma2(x2[3], qtw2[s][3], ffma2(x2[2], qtw2[s][2],
                    ffma2(x2[1], qtw2[s][1], fmul2(x2[0], qtw2[s][0]))));
        float2 fa = u2f(sa); float s1 = fa.x + fa.y;
        float2 fb = u2f(sb); float s2 = fb.x + fb.y;
        float P[8];
#pragma unroll
        for (int s = 0; s < 8; s++) { float2 t = u2f(P2[s]); P[s] = t.x + t.y; }
        s1 = wred(s1); s2 = wred(s2);
#pragma unroll
        for (int s = 0; s < 8; s++) P[s] = wred(P[s]);
        if (lane == 0) {
            *(float4*)&red[par][wp][0] = make_float4(s1, s2, P[0], P[1]);
            *(float4*)&red[par][wp][4] = make_float4(P[2], P[3], P[4], P[5]);
            *(float4*)&red[par][wp][8] = make_float4(P[6], P[7], 0.f, 0.f);
        }
        __syncthreads();
        {
            float4 a0 = *(const float4*)&red[par][0][0];
            float4 a1v = *(const float4*)&red[par][0][4];
            float4 a2 = *(const float4*)&red[par][0][8];
            float4 b0 = *(const float4*)&red[par][1][0];
            float4 b1v = *(const float4*)&red[par][1][4];
            float4 b2 = *(const float4*)&red[par][1][8];
            s1 = a0.x + b0.x; s2 = a0.y + b0.y;
            P[0] = a0.z + b0.z;  P[1] = a0.w + b0.w;
            P[2] = a1v.x + b1v.x; P[3] = a1v.y + b1v.y;
            P[4] = a1v.z + b1v.z; P[5] = a1v.w + b1v.w;
            P[6] = a2.x + b2.x;  P[7] = a2.y + b2.y;
        }
        par ^= 1;
        float m = s1 * (1.0f / DD);
        float var = s2 * (1.0f / DD) - m * m;
        float rstd = rsqrtf(var + LN_EPS);
        float mr = m * rstd;
        float d[8];
#pragma unroll
        for (int s = 0; s < 8; s++)
            d[s] = fmaf(rstd, P[s], fmaf(-mr, qws[s], cb[s]));
        float mx = d[0];
#pragma unroll
        for (int s = 1; s < 8; s++) mx = fmaxf(mx, d[s]);
        float e[8]; float se = 0.f;
#pragma unroll
        for (int s = 0; s < 8; s++) { e[s] = __expf(d[s] - mx); se += e[s]; }
        float inv = 1.0f / se;
        float pe[8];
#pragma unroll
        for (int s = 0; s < 8; s++) {
            float p = e[s] * inv;
            pe[s] = p + ATTN_EPS;
            zacc[s] += pe[s];
            t1acc[s] = fmaf(pe[s], mr, t1acc[s]);
        }
        if (writeAttn && wp == 0) {
            int f = chunk * RPC + r;
            float* ap = attn_out + (size_t)b * SS * FF + f;
            if (tid == 0) ap[0 * FF] = e[0] * inv;
            if (tid == 1) ap[1 * FF] = e[1] * inv;
            if (tid == 2) ap[2 * FF] = e[2] * inv;
            if (tid == 3) ap[3 * FF] = e[3] * inv;
            if (tid == 4) ap[4 * FF] = e[4] * inv;
            if (tid == 5) ap[5 * FF] = e[5] * inv;
            if (tid == 6) ap[6 * FF] = e[6] * inv;
            if (tid == 7) ap[7 * FF] = e[7] * inv;
        }
#pragma unroll
        for (int s = 0; s < 8; s++) {
            float pr = pe[s] * rstd;
            u64 pr2 = pack2(pr, pr);
            acc2[s][0] = ffma2(pr2, x2[0], acc2[s][0]);
            acc2[s][1] = ffma2(pr2, x2[1], acc2[s][1]);
            acc2[s][2] = ffma2(pr2, x2[2], acc2[s][2]);
            acc2[s][3] = ffma2(pr2, x2[3], acc2[s][3]);
        }
    }

    // epilogue: U[s][j] = wf[j]*(A1[s][j] - t1[s]) + bf[j]*z[s]
    float* up = Upart + (((size_t)b * NCHUNK + chunk) * SS) * DD + g0;
#pragma unroll
    for (int s = 0; s < 8; s++) {
        float tt = t1acc[s], zz = zacc[s];
        float o[8];
#pragma unroll
        for (int q = 0; q < 4; q++) {
            float2 av = u2f(acc2[s][q]);
            o[2 * q]     = fmaf(wf[2 * q],     av.x - tt, bf[2 * q] * zz);
            o[2 * q + 1] = fmaf(wf[2 * q + 1], av.y - tt, bf[2 * q + 1] * zz);
        }
        *(float4*)&up[(size_t)s * DD]     = *(float4*)&o[0];
        *(float4*)&up[(size_t)s * DD + 4] = *(float4*)&o[4];
    }
    if (tid == 0) {
        float* zp = Zpart + ((size_t)b * NCHUNK + chunk) * SS;
#pragma unroll
        for (int s = 0; s < 8; s++) zp[s] = zacc[s];
    }
}

// ---------------- reduce partials + normalize ----------------
__global__ void reduce_u(const float* __restrict__ Upart, const float* __restrict__ Zpart,
                         float* __restrict__ Uo) {
    int bs = blockIdx.x;
    int b = bs >> 3, s = bs & 7;
    int tid = threadIdx.x;
    float4 acc = make_float4(0.f, 0.f, 0.f, 0.f);
    float z = 0.f;
    for (int c = 0; c < NCHUNK; c++) {
        const float* up = Upart + (((size_t)b * NCHUNK + c) * SS + s) * DD;
        float4 v = *(const float4*)&up[tid * 4];
        acc.x += v.x; acc.y += v.y; acc.z += v.z; acc.w += v.w;
        z += Zpart[((size_t)b * NCHUNK + c) * SS + s];
    }
    float inv = 1.0f / z;
    acc.x *= inv; acc.y *= inv; acc.z *= inv; acc.w *= inv;
    *(float4*)&Uo[(size_t)bs * DD + tid * 4] = acc;
}

// ---------------- fused GRU combine + MLP LayerNorm ----------------
__global__ void __launch_bounds__(128) gru_ln(
    const float* __restrict__ gi, const float* __restrict__ gh,
    const float* __restrict__ sn, const float* __restrict__ lnw,
    const float* __restrict__ lnb, float* __restrict__ cur, float* __restrict__ hbuf) {
    int row = blockIdx.x;
    int tid = threadIdx.x;
    int dcol = tid * 4;
    size_t base = (size_t)row * (3 * DD) + dcol;
    float4 ir = *(const float4*)&gi[base];
    float4 iz = *(const float4*)&gi[base + DD];
    float4 in_ = *(const float4*)&gi[base + 2 * DD];
    float4 hr = *(const float4*)&gh[base];
    float4 hz = *(const float4*)&gh[base + DD];
    float4 hn = *(const float4*)&gh[base + 2 * DD];
    float4 h = *(const float4*)&sn[(size_t)row * DD + dcol];
    float4 o;
#define GRU1(c) { \
        float r_ = 1.0f / (1.0f + __expf(-(ir.c + hr.c))); \
        float z_ = 1.0f / (1.0f + __expf(-(iz.c + hz.c))); \
        float n_ = tanhf(in_.c + r_ * hn.c); \
        o.c = (1.0f - z_) * n_ + z_ * h.c; }
    GRU1(x) GRU1(y) GRU1(z) GRU1(w)
#undef GRU1
    *(float4*)&cur[(size_t)row * DD + dcol] = o;
    float s1 = o.x + o.y + o.z + o.w;
    float s2 = o.x * o.x + o.y * o.y + o.z * o.z + o.w * o.w;
    s1 = wred(s1); s2 = wred(s2);
    __shared__ float sm[8];
    int lane = tid & 31, wp = tid >> 5;
    if (lane == 0) { sm[wp] = s1; sm[4 + wp] = s2; }
    __syncthreads();
    float st  = sm[0] + sm[1] + sm[2] + sm[3];
    float s2t = sm[4] + sm[5] + sm[6] + sm[7];
    float m = st * (1.0f / DD);
    float var = s2t * (1.0f / DD) - m * m;
    float rstd = rsqrtf(var + LN_EPS);
    float4 wv = *(const float4*)&lnw[dcol];
    float4 bv = *(const float4*)&lnb[dcol];
    float4 y;
    y.x = (o.x - m) * rstd * wv.x + bv.x;
    y.y = (o.y - m) * rstd * wv.y + bv.y;
    y.z = (o.z - m) * rstd * wv.z + bv.z;
    y.w = (o.w - m) * rstd * wv.w + bv.w;
    *(float4*)&hbuf[(size_t)row * DD + dcol] = y;
}

// ---------------- launch ----------------
extern "C" void kernel_launch(void* const* d_in, const int* in_sizes, int n_in,
                              void* d_out, int out_size) {
    const float* slots     = (const float*)d_in[0];
    const float* features  = (const float*)d_in[1];
    const float* w_k       = (const float*)d_in[2];
    const float* w_v       = (const float*)d_in[3];
    const float* w_q       = (const float*)d_in[4];
    const float* ln_feat_w = (const float*)d_in[5];
    const float* ln_feat_b = (const float*)d_in[6];
    const float* ln_slot_w = (const float*)d_in[7];
    const float* ln_slot_b = (const float*)d_in[8];
    const float* gru_w_ih  = (const float*)d_in[9];
    const float* gru_w_hh  = (const float*)d_in[10];
    const float* gru_b_ih  = (const float*)d_in[11];
    const float* gru_b_hh  = (const float*)d_in[12];
    const float* ln_mlp_w  = (const float*)d_in[13];
    const float* ln_mlp_b  = (const float*)d_in[14];
    const float* mlp_w1    = (const float*)d_in[15];
    const float* mlp_b1    = (const float*)d_in[16];
    const float* mlp_w2    = (const float*)d_in[17];
    const float* mlp_b2    = (const float*)d_in[18];

    float *wqk, *wkT, *ihT, *hhT, *cur, *sn, *qt, *Up, *Zp, *un, *upd, *gi, *gh, *hbuf, *a1, *Pp;
    cudaGetSymbolAddress((void**)&wqk, g_wqk);
    cudaGetSymbolAddress((void**)&wkT, g_wkT);
    cudaGetSymbolAddress((void**)&ihT, g_ihT);
    cudaGetSymbolAddress((void**)&hhT, g_hhT);
    cudaGetSymbolAddress((void**)&cur, g_cur);
    cudaGetSymbolAddress((void**)&sn,  g_sn);
    cudaGetSymbolAddress((void**)&qt,  g_qt);
    cudaGetSymbolAddress((void**)&Up,  g_Up);
    cudaGetSymbolAddress((void**)&Zp,  g_Zp);
    cudaGetSymbolAddress((void**)&un,  g_un);
    cudaGetSymbolAddress((void**)&upd, g_upd);
    cudaGetSymbolAddress((void**)&gi,  g_gi);
    cudaGetSymbolAddress((void**)&gh,  g_gh);
    cudaGetSymbolAddress((void**)&hbuf, g_h);
    cudaGetSymbolAddress((void**)&a1,  g_a1);
    cudaGetSymbolAddress((void**)&Pp,  g_P);

    float* out = (float*)d_out;
    float* out_attn = out + BB * SS * DD;
    const int M = BB * SS;  // 256

    cudaMemcpyAsync(cur, slots, (size_t)M * DD * sizeof(float),
                    cudaMemcpyDeviceToDevice, 0);

    // prep: transposes + wqk = SCALE * w_q @ w_k^T
    transpose_k<<<dim3(16, 16), dim3(32, 8)>>>(w_k, wkT, DD, DD);
    transpose_k<<<dim3(16, 48), dim3(32, 8)>>>(gru_w_ih, ihT, 3 * DD, DD);
    transpose_k<<<dim3(16, 48), dim3(32, 8)>>>(gru_w_hh, hhT, 3 * DD, DD);
    gemm_sk<<<dim3(8, 16, 4), 128>>>(w_q, wkT, Pp, DD, DD, DD, 128);
    reduce_c<false, false, false><<<DD * DD / 1024, 256>>>(
        Pp, nullptr, nullptr, wqk, DD, DD, 4, SCALE_QK);

    for (int it = 0; it < 3; it++) {
        ln_rows<<<M, 128>>>(cur, ln_slot_w, ln_slot_b, sn);

        gemm_sk<<<dim3(8, 8, 8), 128>>>(sn, wqk, Pp, M, DD, DD, 64);
        reduce_c<false, false, false><<<M * DD / 1024, 256>>>(
            Pp, nullptr, nullptr, qt, M, DD, 8, 1.0f);

        attn_stream<<<dim3(NCHUNK, BB), 64>>>(
            features, qt, ln_feat_w, ln_feat_b, Up, Zp, out_attn, it == 2 ? 1 : 0);
        reduce_u<<<M, 128>>>(Up, Zp, un);

        gemm_sk<<<dim3(8, 8, 8), 128>>>(un, w_v, Pp, M, DD, DD, 64);
        reduce_c<false, false, false><<<M * DD / 1024, 256>>>(
            Pp, nullptr, nullptr, upd, M, DD, 8, 1.0f);

        gemm_sk<<<dim3(24, 8, 4), 128>>>(upd, ihT, Pp, M, 3 * DD, DD, 128);
        reduce_c<true, false, false><<<M * 3 * DD / 1024, 256>>>(
            Pp, gru_b_ih, nullptr, gi, M, 3 * DD, 4, 1.0f);

        gemm_sk<<<dim3(24, 8, 4), 128>>>(sn, hhT, Pp, M, 3 * DD, DD, 128);
        reduce_c<true, false, false><<<M * 3 * DD / 1024, 256>>>(
            Pp, gru_b_hh, nullptr, gh, M, 3 * DD, 4, 1.0f);

        gru_ln<<<M, 128>>>(gi, gh, sn, ln_mlp_w, ln_mlp_b, cur, hbuf);

        gemm_sk<<<dim3(32, 8, 4), 128>>>(hbuf, mlp_w1, Pp, M, HH, DD, 128);
        reduce_c<true, true, false><<<M * HH / 1024, 256>>>(
            Pp, mlp_b1, nullptr, a1, M, HH, 4, 1.0f);

        float* dst = (it == 2) ? out : cur;
        gemm_sk<<<dim3(8, 8, 8), 128>>>(a1, mlp_w2, Pp, M, DD, HH, 256);
        reduce_c<true, false, true><<<M * DD / 1024, 256>>>(
            Pp, mlp_b2, cur, dst, M, DD, 8, 1.0f);
    }
}

// round 13
// speedup vs baseline: 1.3965x; 1.0116x over previous
#include <cuda_runtime.h>
#include <cuda_bf16.h>
#include <math.h>

// Shapes
#define BB 32
#define FF 4096
#define SS 8
#define DD 512
#define HH 2048
#define NCHUNK 32
#define RPC (FF / NCHUNK)   // 128 rows per chunk
#define SCALE_QK 0.044194173824159216f
#define LN_EPS 1e-5f
#define ATTN_EPS 1e-8f

typedef unsigned long long u64;

// ---------------- scratch ----------------
__device__ float g_wqk [DD * DD];
__device__ float g_wkT [DD * DD];
__device__ float g_ihT [DD * 3 * DD];
__device__ float g_hhT [DD * 3 * DD];
__device__ float g_cur [BB * SS * DD];
__device__ float g_sn  [BB * SS * DD];
__device__ float g_qt  [BB * SS * DD];
__device__ float g_Up  [BB * NCHUNK * SS * DD];
__device__ float g_Zp  [BB * NCHUNK * SS];
__device__ float g_un  [BB * SS * DD];
__device__ float g_upd [BB * SS * DD];
__device__ float g_gi  [BB * SS * 3 * DD];
__device__ float g_gh  [BB * SS * 3 * DD];
__device__ float g_h   [BB * SS * DD];
__device__ float g_a1  [BB * SS * HH];
__device__ float g_P   [8 * 1024 * 1024];   // split-K partials (32 MB)

// ---------------- helpers ----------------
__device__ __forceinline__ float wred(float v) {
    v += __shfl_xor_sync(0xffffffffu, v, 16);
    v += __shfl_xor_sync(0xffffffffu, v, 8);
    v += __shfl_xor_sync(0xffffffffu, v, 4);
    v += __shfl_xor_sync(0xffffffffu, v, 2);
    v += __shfl_xor_sync(0xffffffffu, v, 1);
    return v;
}
__device__ __forceinline__ u64 pack2(float lo, float hi) {
    u64 r; asm("mov.b64 %0, {%1,%2};" : "=l"(r) : "f"(lo), "f"(hi)); return r;
}
__device__ __forceinline__ float2 u2f(u64 v) {
    float2 r; asm("mov.b64 {%0,%1}, %2;" : "=f"(r.x), "=f"(r.y) : "l"(v)); return r;
}
__device__ __forceinline__ u64 ffma2(u64 a, u64 b, u64 c) {
    u64 d; asm("fma.rn.f32x2 %0, %1, %2, %3;" : "=l"(d) : "l"(a), "l"(b), "l"(c)); return d;
}
__device__ __forceinline__ u64 fmul2(u64 a, u64 b) {
    u64 d; asm("mul.rn.f32x2 %0, %1, %2;" : "=l"(d) : "l"(a), "l"(b)); return d;
}
__device__ __forceinline__ u64 fadd2(u64 a, u64 b) {
    u64 d; asm("add.rn.f32x2 %0, %1, %2;" : "=l"(d) : "l"(a), "l"(b)); return d;
}

// ---------------- transpose (32x32 tiles, block 32x8) ----------------
__global__ void transpose_k(const float* __restrict__ A, float* __restrict__ At,
                            int R, int C) {
    __shared__ float t[32][33];
    int rb = blockIdx.y * 32, cb = blockIdx.x * 32;
    int tx = threadIdx.x, ty = threadIdx.y;
#pragma unroll
    for (int i = 0; i < 4; i++)
        t[ty + 8 * i][tx] = A[(size_t)(rb + ty + 8 * i) * C + cb + tx];
    __syncthreads();
#pragma unroll
    for (int i = 0; i < 4; i++)
        At[(size_t)(cb + ty + 8 * i) * R + rb + tx] = t[tx][ty + 8 * i];
}

// ---------------- LayerNorm rows of width 512 ----------------
__global__ void ln_rows(const float* __restrict__ X, const float* __restrict__ w,
                        const float* __restrict__ b, float* __restrict__ Y) {
    int row = blockIdx.x;
    int tid = threadIdx.x;
    const float* x = X + (size_t)row * DD;
    float4 v = *(const float4*)&x[tid * 4];
    float s1 = v.x + v.y + v.z + v.w;
    float s2 = v.x * v.x + v.y * v.y + v.z * v.z + v.w * v.w;
    s1 = wred(s1); s2 = wred(s2);
    __shared__ float sm[8];
    int lane = tid & 31, wp = tid >> 5;
    if (lane == 0) { sm[wp] = s1; sm[4 + wp] = s2; }
    __syncthreads();
    float st  = sm[0] + sm[1] + sm[2] + sm[3];
    float s2t = sm[4] + sm[5] + sm[6] + sm[7];
    float m = st * (1.0f / DD);
    float var = s2t * (1.0f / DD) - m * m;
    float rstd = rsqrtf(var + LN_EPS);
    float4 wv = *(const float4*)&w[tid * 4];
    float4 bv = *(const float4*)&b[tid * 4];
    float4 o;
    o.x = (v.x - m) * rstd * wv.x + bv.x;
    o.y = (v.y - m) * rstd * wv.y + bv.y;
    o.z = (v.z - m) * rstd * wv.z + bv.z;
    o.w = (v.w - m) * rstd * wv.w + bv.w;
    *(float4*)&Y[(size_t)row * DD + tid * 4] = o;
}

// ---------------- split-K GEMM core (tile 32M x 64N, block 128) ----------------
__device__ __forceinline__ void gemm_core(
    const float* __restrict__ A, const float* __restrict__ B,
    float* __restrict__ Pout, int M, int N, int K, int k0, int Kr) {
    __shared__ float As[32][36];
    __shared__ float Bs[32][64];
    int tid = threadIdx.x;
    int tx = tid & 15;
    int ty = tid >> 4;
    int tileM = blockIdx.y * 32;
    int tileN = blockIdx.x * 64;
    float acc[4][4];
#pragma unroll
    for (int i = 0; i < 4; i++)
#pragma unroll
        for (int j = 0; j < 4; j++) acc[i][j] = 0.f;

    for (int kc = k0; kc < k0 + Kr; kc += 32) {
#pragma unroll
        for (int i = 0; i < 2; i++) {
            int f = tid + 128 * i;
            int m = f >> 3;
            int k4 = (f & 7) * 4;
            float4 v = *(const float4*)&A[(size_t)(tileM + m) * K + kc + k4];
            As[k4 + 0][m] = v.x;
            As[k4 + 1][m] = v.y;
            As[k4 + 2][m] = v.z;
            As[k4 + 3][m] = v.w;
        }
#pragma unroll
        for (int i = 0; i < 4; i++) {
            int f = tid + 128 * i;
            int k = f >> 4;
            int n4 = (f & 15) * 4;
            *(float4*)&Bs[k][n4] = *(const float4*)&B[(size_t)(kc + k) * N + tileN + n4];
        }
        __syncthreads();
#pragma unroll
        for (int k = 0; k < 32; k++) {
            float4 av = *(const float4*)&As[k][ty * 4];
            float4 b4 = *(const float4*)&Bs[k][tx * 4];
            float a[4] = {av.x, av.y, av.z, av.w};
#pragma unroll
            for (int i = 0; i < 4; i++) {
                acc[i][0] = fmaf(a[i], b4.x, acc[i][0]);
                acc[i][1] = fmaf(a[i], b4.y, acc[i][1]);
                acc[i][2] = fmaf(a[i], b4.z, acc[i][2]);
                acc[i][3] = fmaf(a[i], b4.w, acc[i][3]);
            }
        }
        __syncthreads();
    }
    int col = tileN + tx * 4;
#pragma unroll
    for (int i = 0; i < 4; i++) {
        int row = tileM + ty * 4 + i;
        *(float4*)&Pout[(size_t)row * N + col] =
            make_float4(acc[i][0], acc[i][1], acc[i][2], acc[i][3]);
    }
}

__global__ void __launch_bounds__(128) gemm_sk(
    const float* __restrict__ A, const float* __restrict__ B,
    float* __restrict__ P, int M, int N, int K, int Kr) {
    gemm_core(A, B, P + (size_t)blockIdx.z * M * N, M, N, K, blockIdx.z * Kr, Kr);
}

// batched two-operand-pair variant: z < halfz -> (A0,B0), else (A1,B1)
__global__ void __launch_bounds__(128) gemm_sk2(
    const float* __restrict__ A0, const float* __restrict__ B0,
    const float* __restrict__ A1, const float* __restrict__ B1,
    float* __restrict__ P, int M, int N, int K, int Kr, int halfz) {
    int z = blockIdx.z;
    const float* A = (z < halfz) ? A0 : A1;
    const float* B = (z < halfz) ? B0 : B1;
    int zz = (z < halfz) ? z : z - halfz;
    gemm_core(A, B, P + (size_t)z * M * N, M, N, K, zz * Kr, Kr);
}

// ---------------- split-K reduce + epilogue ----------------
template<bool BIAS, bool RELU, bool RES>
__global__ void __launch_bounds__(256) reduce_c(
    const float* __restrict__ P, const float* __restrict__ bias,
    const float* __restrict__ res, float* __restrict__ C,
    int M, int N, int nsplit, float alpha) {
    int i4 = (blockIdx.x * 256 + threadIdx.x) * 4;
    size_t MN = (size_t)M * N;
    float4 acc = *(const float4*)&P[i4];
    for (int z = 1; z < nsplit; z++) {
        float4 v = *(const float4*)&P[(size_t)z * MN + i4];
        acc.x += v.x; acc.y += v.y; acc.z += v.z; acc.w += v.w;
    }
    acc.x *= alpha; acc.y *= alpha; acc.z *= alpha; acc.w *= alpha;
    if (BIAS) {
        int col = i4 % N;
        float4 bv = *(const float4*)&bias[col];
        acc.x += bv.x; acc.y += bv.y; acc.z += bv.z; acc.w += bv.w;
    }
    if (RELU) {
        acc.x = fmaxf(acc.x, 0.f); acc.y = fmaxf(acc.y, 0.f);
        acc.z = fmaxf(acc.z, 0.f); acc.w = fmaxf(acc.w, 0.f);
    }
    if (RES) {
        float4 rv = *(const float4*)&res[i4];
        acc.x += rv.x; acc.y += rv.y; acc.z += rv.z; acc.w += rv.w;
    }
    *(float4*)&C[i4] = acc;
}

// ---------------- streaming attention pass ----------------
// grid (NCHUNK, BB), block 128 = two warp-PAIRS; pair p handles rows r+p.
// One __syncthreads per 2 rows. Cross-pair accumulator combine in epilogue.
__global__ void __launch_bounds__(128) attn_stream(
    const float* __restrict__ feats, const float* __restrict__ qt,
    const float* __restrict__ lnw, const float* __restrict__ lnb,
    float* __restrict__ Upart, float* __restrict__ Zpart,
    float* __restrict__ attn_out, int writeAttn) {
    const int b = blockIdx.y, chunk = blockIdx.x;
    const int tid = threadIdx.x;
    const int p   = tid >> 6;          // pair 0/1
    const int t64 = tid & 63;          // thread within pair
    const int wpp = (tid >> 5) & 1;    // warp within pair
    const int lane = tid & 31;
    const int g0 = t64 * 8;

    __shared__ float red[2][2][2][16];   // [parity][pair][warp-in-pair][16]
    __shared__ float red0[2][2][16];     // [pair][warp-in-pair][16]
    __shared__ float sAcc[64][8][8];     // pair-1 accumulator staging
    __shared__ float sZT[17];            // pair-1 z[8] + t1[8]

    float wf[8], bf[8];
    *(float4*)&wf[0] = *(const float4*)&lnw[g0];
    *(float4*)&wf[4] = *(const float4*)&lnw[g0 + 4];
    *(float4*)&bf[0] = *(const float4*)&lnb[g0];
    *(float4*)&bf[4] = *(const float4*)&lnb[g0 + 4];

    u64 qtw2[8][4];
    float cb[8], qws[8];
#pragma unroll
    for (int s = 0; s < 8; s++) {
        float q[8];
        *(float4*)&q[0] = *(const float4*)&qt[((size_t)b * 8 + s) * DD + g0];
        *(float4*)&q[4] = *(const float4*)&qt[((size_t)b * 8 + s) * DD + g0 + 4];
        float cbp = 0.f, qp = 0.f, w[8];
#pragma unroll
        for (int j = 0; j < 8; j++) {
            w[j] = q[j] * wf[j];
            cbp = fmaf(q[j], bf[j], cbp);
            qp += w[j];
        }
        qtw2[s][0] = pack2(w[0], w[1]);
        qtw2[s][1] = pack2(w[2], w[3]);
        qtw2[s][2] = pack2(w[4], w[5]);
        qtw2[s][3] = pack2(w[6], w[7]);
        cb[s] = cbp; qws[s] = qp;
    }
#pragma unroll
    for (int s = 0; s < 8; s++) { cb[s] = wred(cb[s]); qws[s] = wred(qws[s]); }
    if (lane == 0) {
        *(float4*)&red0[p][wpp][0]  = make_float4(cb[0], cb[1], cb[2], cb[3]);
        *(float4*)&red0[p][wpp][4]  = make_float4(cb[4], cb[5], cb[6], cb[7]);
        *(float4*)&red0[p][wpp][8]  = make_float4(qws[0], qws[1], qws[2], qws[3]);
        *(float4*)&red0[p][wpp][12] = make_float4(qws[4], qws[5], qws[6], qws[7]);
    }
    __syncthreads();
#pragma unroll
    for (int s = 0; s < 8; s++) {
        cb[s]  = red0[p][0][s]     + red0[p][1][s];
        qws[s] = red0[p][0][8 + s] + red0[p][1][8 + s];
    }
    __syncthreads();

    u64 acc2[8][4];
#pragma unroll
    for (int s = 0; s < 8; s++)
#pragma unroll
        for (int q = 0; q < 4; q++) acc2[s][q] = 0ull;
    float zacc[8]  = {0.f, 0.f, 0.f, 0.f, 0.f, 0.f, 0.f, 0.f};
    float t1acc[8] = {0.f, 0.f, 0.f, 0.f, 0.f, 0.f, 0.f, 0.f};

    // pair p streams rows p, p+2, ..., RPC-2+p
    const float* fp = feats + ((size_t)b * FF + (size_t)chunk * RPC + p) * DD + g0;
    ulonglong2 xa = *(const ulonglong2*)fp;
    ulonglong2 xb = *(const ulonglong2*)(fp + 4);
    int par = 0;

    for (int r = 0; r < RPC; r += 2) {
        u64 x2[4] = {xa.x, xa.y, xb.x, xb.y};
        if (r + 2 < RPC) {
            const float* np = fp + (size_t)(r + 2) * DD;
            xa = *(const ulonglong2*)np;
            xb = *(const ulonglong2*)(np + 4);
        }
        u64 sa = fadd2(fadd2(x2[0], x2[1]), fadd2(x2[2], x2[3]));
        u64 sb = ffma2(x2[3], x2[3], ffma2(x2[2], x2[2],
                 ffma2(x2[1], x2[1], fmul2(x2[0], x2[0]))));
        u64 P2[8];
#pragma unroll
        for (int s = 0; s < 8; s++)
            P2[s] = ffma2(x2[3], qtw2[s][3], ffma2(x2[2], qtw2[s][2],
                    ffma2(x2[1], qtw2[s][1], fmul2(x2[0], qtw2[s][0]))));
        float2 fa = u2f(sa); float s1 = fa.x + fa.y;
        float2 fb = u2f(sb); float s2 = fb.x + fb.y;
        float P[8];
#pragma unroll
        for (int s = 0; s < 8; s++) { float2 t = u2f(P2[s]); P[s] = t.x + t.y; }
        s1 = wred(s1); s2 = wred(s2);
#pragma unroll
        for (int s = 0; s < 8; s++) P[s] = wred(P[s]);
        if (lane == 0) {
            *(float4*)&red[par][p][wpp][0] = make_float4(s1, s2, P[0], P[1]);
            *(float4*)&red[par][p][wpp][4] = make_float4(P[2], P[3], P[4], P[5]);
            *(float4*)&red[par][p][wpp][8] = make_float4(P[6], P[7], 0.f, 0.f);
        }
        __syncthreads();
        {
            float4 a0 = *(const float4*)&red[par][p][0][0];
            float4 a1v = *(const float4*)&red[par][p][0][4];
            float4 a2 = *(const float4*)&red[par][p][0][8];
            float4 b0 = *(const float4*)&red[par][p][1][0];
            float4 b1v = *(const float4*)&red[par][p][1][4];
            float4 b2 = *(const float4*)&red[par][p][1][8];
            s1 = a0.x + b0.x; s2 = a0.y + b0.y;
            P[0] = a0.z + b0.z;  P[1] = a0.w + b0.w;
            P[2] = a1v.x + b1v.x; P[3] = a1v.y + b1v.y;
            P[4] = a1v.z + b1v.z; P[5] = a1v.w + b1v.w;
            P[6] = a2.x + b2.x;  P[7] = a2.y + b2.y;
        }
        par ^= 1;
        float m = s1 * (1.0f / DD);
        float var = s2 * (1.0f / DD) - m * m;
        float rstd = rsqrtf(var + LN_EPS);
        float mr = m * rstd;
        float d[8];
#pragma unroll
        for (int s = 0; s < 8; s++)
            d[s] = fmaf(rstd, P[s], fmaf(-mr, qws[s], cb[s]));
        float mx = d[0];
#pragma unroll
        for (int s = 1; s < 8; s++) mx = fmaxf(mx, d[s]);
        float e[8]; float se = 0.f;
#pragma unroll
        for (int s = 0; s < 8; s++) { e[s] = __expf(d[s] - mx); se += e[s]; }
        float inv = 1.0f / se;
        float pe[8];
#pragma unroll
        for (int s = 0; s < 8; s++) {
            float pp = e[s] * inv;
            pe[s] = pp + ATTN_EPS;
            zacc[s] += pe[s];
            t1acc[s] = fmaf(pe[s], mr, t1acc[s]);
        }
        if (writeAttn && wpp == 0) {
            int f = chunk * RPC + r + p;
            float* ap = attn_out + (size_t)b * SS * FF + f;
            if (t64 == 0) ap[0 * FF] = e[0] * inv;
            if (t64 == 1) ap[1 * FF] = e[1] * inv;
            if (t64 == 2) ap[2 * FF] = e[2] * inv;
            if (t64 == 3) ap[3 * FF] = e[3] * inv;
            if (t64 == 4) ap[4 * FF] = e[4] * inv;
            if (t64 == 5) ap[5 * FF] = e[5] * inv;
            if (t64 == 6) ap[6 * FF] = e[6] * inv;
            if (t64 == 7) ap[7 * FF] = e[7] * inv;
        }
#pragma unroll
        for (int s = 0; s < 8; s++) {
            float pr = pe[s] * rstd;
            u64 pr2 = pack2(pr, pr);
            acc2[s][0] = ffma2(pr2, x2[0], acc2[s][0]);
            acc2[s][1] = ffma2(pr2, x2[1], acc2[s][1]);
            acc2[s][2] = ffma2(pr2, x2[2], acc2[s][2]);
            acc2[s][3] = ffma2(pr2, x2[3], acc2[s][3]);
        }
    }

    // cross-pair combine: pair 1 stages, pair 0 finalizes
    if (p == 1) {
#pragma unroll
        for (int s = 0; s < 8; s++)
#pragma unroll
            for (int q = 0; q < 4; q++) {
                float2 av = u2f(acc2[s][q]);
                sAcc[t64][s][2 * q]     = av.x;
                sAcc[t64][s][2 * q + 1] = av.y;
            }
        if (t64 == 0) {
#pragma unroll
            for (int s = 0; s < 8; s++) { sZT[s] = zacc[s]; sZT[8 + s] = t1acc[s]; }
        }
    }
    __syncthreads();
    if (p == 0) {
        float* up = Upart + (((size_t)b * NCHUNK + chunk) * SS) * DD + g0;
#pragma unroll
        for (int s = 0; s < 8; s++) {
            float zz = zacc[s] + sZT[s];
            float tt = t1acc[s] + sZT[8 + s];
            float o[8];
#pragma unroll
            for (int q = 0; q < 4; q++) {
                float2 av = u2f(acc2[s][q]);
                float a0 = av.x + sAcc[t64][s][2 * q];
                float a1 = av.y + sAcc[t64][s][2 * q + 1];
                o[2 * q]     = fmaf(wf[2 * q],     a0 - tt, bf[2 * q] * zz);
                o[2 * q + 1] = fmaf(wf[2 * q + 1], a1 - tt, bf[2 * q + 1] * zz);
            }
            *(float4*)&up[(size_t)s * DD]     = *(float4*)&o[0];
            *(float4*)&up[(size_t)s * DD + 4] = *(float4*)&o[4];
        }
        if (t64 == 0) {
            float* zp = Zpart + ((size_t)b * NCHUNK + chunk) * SS;
#pragma unroll
            for (int s = 0; s < 8; s++) zp[s] = zacc[s] + sZT[s];
        }
    }
}

// ---------------- reduce partials + normalize ----------------
__global__ void reduce_u(const float* __restrict__ Upart, const float* __restrict__ Zpart,
                         float* __restrict__ Uo) {
    int bs = blockIdx.x;
    int b = bs >> 3, s = bs & 7;
    int tid = threadIdx.x;
    float4 acc = make_float4(0.f, 0.f, 0.f, 0.f);
    float z = 0.f;
    for (int c = 0; c < NCHUNK; c++) {
        const float* up = Upart + (((size_t)b * NCHUNK + c) * SS + s) * DD;
        float4 v = *(const float4*)&up[tid * 4];
        acc.x += v.x; acc.y += v.y; acc.z += v.z; acc.w += v.w;
        z += Zpart[((size_t)b * NCHUNK + c) * SS + s];
    }
    float inv = 1.0f / z;
    acc.x *= inv; acc.y *= inv; acc.z *= inv; acc.w *= inv;
    *(float4*)&Uo[(size_t)bs * DD + tid * 4] = acc;
}

// ---------------- fused GRU combine + MLP LayerNorm ----------------
__global__ void __launch_bounds__(128) gru_ln(
    const float* __restrict__ gi, const float* __restrict__ gh,
    const float* __restrict__ sn, const float* __restrict__ lnw,
    const float* __restrict__ lnb, float* __restrict__ cur, float* __restrict__ hbuf) {
    int row = blockIdx.x;
    int tid = threadIdx.x;
    int dcol = tid * 4;
    size_t base = (size_t)row * (3 * DD) + dcol;
    float4 ir = *(const float4*)&gi[base];
    float4 iz = *(const float4*)&gi[base + DD];
    float4 in_ = *(const float4*)&gi[base + 2 * DD];
    float4 hr = *(const float4*)&gh[base];
    float4 hz = *(const float4*)&gh[base + DD];
    float4 hn = *(const float4*)&gh[base + 2 * DD];
    float4 h = *(const float4*)&sn[(size_t)row * DD + dcol];
    float4 o;
#define GRU1(c) { \
        float r_ = 1.0f / (1.0f + __expf(-(ir.c + hr.c))); \
        float z_ = 1.0f / (1.0f + __expf(-(iz.c + hz.c))); \
        float n_ = tanhf(in_.c + r_ * hn.c); \
        o.c = (1.0f - z_) * n_ + z_ * h.c; }
    GRU1(x) GRU1(y) GRU1(z) GRU1(w)
#undef GRU1
    *(float4*)&cur[(size_t)row * DD + dcol] = o;
    float s1 = o.x + o.y + o.z + o.w;
    float s2 = o.x * o.x + o.y * o.y + o.z * o.z + o.w * o.w;
    s1 = wred(s1); s2 = wred(s2);
    __shared__ float sm[8];
    int lane = tid & 31, wp = tid >> 5;
    if (lane == 0) { sm[wp] = s1; sm[4 + wp] = s2; }
    __syncthreads();
    float st  = sm[0] + sm[1] + sm[2] + sm[3];
    float s2t = sm[4] + sm[5] + sm[6] + sm[7];
    float m = st * (1.0f / DD);
    float var = s2t * (1.0f / DD) - m * m;
    float rstd = rsqrtf(var + LN_EPS);
    float4 wv = *(const float4*)&lnw[dcol];
    float4 bv = *(const float4*)&lnb[dcol];
    float4 y;
    y.x = (o.x - m) * rstd * wv.x + bv.x;
    y.y = (o.y - m) * rstd * wv.y + bv.y;
    y.z = (o.z - m) * rstd * wv.z + bv.z;
    y.w = (o.w - m) * rstd * wv.w + bv.w;
    *(float4*)&hbuf[(size_t)row * DD + dcol] = y;
}

// ---------------- launch ----------------
extern "C" void kernel_launch(void* const* d_in, const int* in_sizes, int n_in,
                              void* d_out, int out_size) {
    const float* slots     = (const float*)d_in[0];
    const float* features  = (const float*)d_in[1];
    const float* w_k       = (const float*)d_in[2];
    const float* w_v       = (const float*)d_in[3];
    const float* w_q       = (const float*)d_in[4];
    const float* ln_feat_w = (const float*)d_in[5];
    const float* ln_feat_b = (const float*)d_in[6];
    const float* ln_slot_w = (const float*)d_in[7];
    const float* ln_slot_b = (const float*)d_in[8];
    const float* gru_w_ih  = (const float*)d_in[9];
    const float* gru_w_hh  = (const float*)d_in[10];
    const float* gru_b_ih  = (const float*)d_in[11];
    const float* gru_b_hh  = (const float*)d_in[12];
    const float* ln_mlp_w  = (const float*)d_in[13];
    const float* ln_mlp_b  = (const float*)d_in[14];
    const float* mlp_w1    = (const float*)d_in[15];
    const float* mlp_b1    = (const float*)d_in[16];
    const float* mlp_w2    = (const float*)d_in[17];
    const float* mlp_b2    = (const float*)d_in[18];

    float *wqk, *wkT, *ihT, *hhT, *cur, *sn, *qt, *Up, *Zp, *un, *upd, *gi, *gh, *hbuf, *a1, *Pp;
    cudaGetSymbolAddress((void**)&wqk, g_wqk);
    cudaGetSymbolAddress((void**)&wkT, g_wkT);
    cudaGetSymbolAddress((void**)&ihT, g_ihT);
    cudaGetSymbolAddress((void**)&hhT, g_hhT);
    cudaGetSymbolAddress((void**)&cur, g_cur);
    cudaGetSymbolAddress((void**)&sn,  g_sn);
    cudaGetSymbolAddress((void**)&qt,  g_qt);
    cudaGetSymbolAddress((void**)&Up,  g_Up);
    cudaGetSymbolAddress((void**)&Zp,  g_Zp);
    cudaGetSymbolAddress((void**)&un,  g_un);
    cudaGetSymbolAddress((void**)&upd, g_upd);
    cudaGetSymbolAddress((void**)&gi,  g_gi);
    cudaGetSymbolAddress((void**)&gh,  g_gh);
    cudaGetSymbolAddress((void**)&hbuf, g_h);
    cudaGetSymbolAddress((void**)&a1,  g_a1);
    cudaGetSymbolAddress((void**)&Pp,  g_P);

    float* out = (float*)d_out;
    float* out_attn = out + BB * SS * DD;
    const int M = BB * SS;  // 256

    cudaMemcpyAsync(cur, slots, (size_t)M * DD * sizeof(float),
                    cudaMemcpyDeviceToDevice, 0);

    // prep: transposes + wqk = SCALE * w_q @ w_k^T
    transpose_k<<<dim3(16, 16), dim3(32, 8)>>>(w_k, wkT, DD, DD);
    transpose_k<<<dim3(16, 48), dim3(32, 8)>>>(gru_w_ih, ihT, 3 * DD, DD);
    transpose_k<<<dim3(16, 48), dim3(32, 8)>>>(gru_w_hh, hhT, 3 * DD, DD);
    gemm_sk<<<dim3(8, 16, 8), 128>>>(w_q, wkT, Pp, DD, DD, DD, 64);
    reduce_c<false, false, false><<<DD * DD / 1024, 256>>>(
        Pp, nullptr, nullptr, wqk, DD, DD, 8, SCALE_QK);

    for (int it = 0; it < 3; it++) {
        ln_rows<<<M, 128>>>(cur, ln_slot_w, ln_slot_b, sn);

        gemm_sk<<<dim3(8, 8, 16), 128>>>(sn, wqk, Pp, M, DD, DD, 32);
        reduce_c<false, false, false><<<M * DD / 1024, 256>>>(
            Pp, nullptr, nullptr, qt, M, DD, 16, 1.0f);

        attn_stream<<<dim3(NCHUNK, BB), 128>>>(
            features, qt, ln_feat_w, ln_feat_b, Up, Zp, out_attn, it == 2 ? 1 : 0);
        reduce_u<<<M, 128>>>(Up, Zp, un);

        gemm_sk<<<dim3(8, 8, 16), 128>>>(un, w_v, Pp, M, DD, DD, 32);
        reduce_c<false, false, false><<<M * DD / 1024, 256>>>(
            Pp, nullptr, nullptr, upd, M, DD, 16, 1.0f);

        // gi and gh batched: z in [0,8) -> gi partials, [8,16) -> gh partials
        gemm_sk2<<<dim3(24, 8, 16), 128>>>(upd, ihT, sn, hhT, Pp, M, 3 * DD, DD, 64, 8);
        reduce_c<true, false, false><<<M * 3 * DD / 1024, 256>>>(
            Pp, gru_b_ih, nullptr, gi, M, 3 * DD, 8, 1.0f);
        reduce_c<true, false, false><<<M * 3 * DD / 1024, 256>>>(
            Pp + (size_t)8 * M * 3 * DD, gru_b_hh, nullptr, gh, M, 3 * DD, 8, 1.0f);

        gru_ln<<<M, 128>>>(gi, gh, sn, ln_mlp_w, ln_mlp_b, cur, hbuf);

        gemm_sk<<<dim3(32, 8, 8), 128>>>(hbuf, mlp_w1, Pp, M, HH, DD, 64);
        reduce_c<true, true, false><<<M * HH / 1024, 256>>>(
            Pp, mlp_b1, nullptr, a1, M, HH, 8, 1.0f);

        float* dst = (it == 2) ? out : cur;
        gemm_sk<<<dim3(8, 8, 16), 128>>>(a1, mlp_w2, Pp, M, DD, HH, 128);
        reduce_c<true, false, true><<<M * DD / 1024, 256>>>(
            Pp, mlp_b2, cur, dst, M, DD, 16, 1.0f);
    }
}